// round 13
// baseline (speedup 1.0000x reference)
#include <cuda_runtime.h>
#include <cuda_bf16.h>
#include <cstdint>

#define A_   50
#define T_   50
#define HID_ 128
#define H_   32
#define C_   16
#define B_   32
#define S_   2450          // T_*(A_-1)
#define SP_  2496          // S_ padded to 64
#define HC_  512           // H_*C_
#define NEG_SLOPE 0.2f
#define NB   51            // buckets 0..50
#define OUT4 10240000      // total float4 in output
#define NPART 2            // s-dimension partitions

// ---------------- scratch (device globals; no allocations allowed) --------
__device__ float g_vdst[H_ * HID_];                         // [h][d]
__device__ __align__(16) __nv_bfloat16 g_Whi[HC_ * HID_];   // [n][k]
__device__ __align__(16) __nv_bfloat16 g_Wlo[HC_ * HID_];   // [n][k]
__device__ __align__(16) __nv_bfloat16 g_Xhi[(size_t)B_ * SP_ * HID_];  // 20.4 MB
__device__ __align__(16) __nv_bfloat16 g_Xlo[(size_t)B_ * SP_ * HID_];
__device__ float g_eth[B_ * H_ * 64];                       // sorted thresholds (+INF pad)
__device__ float g_e1[B_ * H_ * T_];
__device__ float g_e2[B_ * H_ * T_];
__device__ int   g_perm[B_ * H_ * T_];
__device__ __align__(16) float g_bkt[(size_t)B_ * H_ * NPART * 2 * NB * 16];  // 13.4 MB
__device__ float g_qbk[B_ * H_ * NPART * 2 * NB];

__device__ __forceinline__ uint32_t smem_u32(const void* p) {
    uint32_t a;
    asm("{ .reg .u64 t; cvta.to.shared.u64 t, %1; cvt.u32.u64 %0, t; }" : "=r"(a) : "l"(p));
    return a;
}

// mma.sync m16n8k16 row.col f32.bf16.bf16.f32
__device__ __forceinline__ void mma_bf16(float* c, const uint32_t* a, const uint32_t* b) {
    asm volatile(
        "mma.sync.aligned.m16n8k16.row.col.f32.bf16.bf16.f32 "
        "{%0,%1,%2,%3}, {%4,%5,%6,%7}, {%8,%9}, {%0,%1,%2,%3};"
        : "+f"(c[0]), "+f"(c[1]), "+f"(c[2]), "+f"(c[3])
        : "r"(a[0]), "r"(a[1]), "r"(a[2]), "r"(a[3]), "r"(b[0]), "r"(b[1]));
}

#define LDMX4(r0, r1, r2, r3, addr) \
    asm volatile("ldmatrix.sync.aligned.m8n8.x4.shared.b16 {%0,%1,%2,%3}, [%4];" \
        : "=r"(r0), "=r"(r1), "=r"(r2), "=r"(r3) : "r"(addr))

#define CP_ASYNC16(dst, src) \
    asm volatile("cp.async.ca.shared.global [%0], [%1], 16;" :: "r"(dst), "l"(src))
#define CP_COMMIT() asm volatile("cp.async.commit_group;")
#define CP_WAIT0()  asm volatile("cp.async.wait_group 0;" ::: "memory")

// ---- fused kernel smem layout (bytes); M=64 rows, 4 heads (N=64) ----
#define ASTR   136
#define OSTR   68
#define NT     39                      // SP_/64
#define FB_WHI  0                      // 17408
#define FB_WLO  17408                  // 17408
#define FB_AHI  34816                  // 17408
#define FB_ALO  52224                  // 17408
#define FB_OUTS FB_AHI                 // outs aliases A_hi ONLY (A_lo stays live)
#define FB_BKT  69632                  // 4h*2arr*53*16*4 = 27136
#define FB_QBK  96768                  // 4*2*53*4 = 1696
#define FB_ETH  98464                  // 4*64*4 = 1024
#define FB_ASC  99488                  // 4*16*4 = 256
#define FB_QS1  99744                  // 4*64*4
#define FB_QS2  100768
#define FB_RO   101792
#define SMEM_FUSED 102816
#define TRASH  816                     // row 51 within a (hl,arr) region (53 rows)

// ---------------- prep: bf16-split W, contract att_dst into v_dst ----------
__global__ void prep_kernel(const float* __restrict__ W,
                            const float* __restrict__ att_dst) {
    int idx = blockIdx.x * blockDim.x + threadIdx.x;
    if (idx < HID_ * HC_) {
        float w = W[idx];
        __nv_bfloat16 hi = __float2bfloat16(w);
        g_Whi[idx] = hi;
        g_Wlo[idx] = __float2bfloat16(w - __bfloat162float(hi));
    }
    if (idx < H_ * HID_) {
        int h = idx / HID_, d = idx % HID_;
        float s2 = 0.f;
        #pragma unroll
        for (int c = 0; c < C_; c++)
            s2 += W[(h * C_ + c) * HID_ + d] * att_dst[h * C_ + c];
        g_vdst[idx] = s2;
    }
}

// ---------------- xprep: split X rows (non-ego, s-indexed) to bf16 hi/lo ---
__global__ __launch_bounds__(256) void xprep_kernel(const float* __restrict__ hin) {
    int idx = blockIdx.x * 256 + threadIdx.x;          // one float4 (4 k) per iter
    const int total = B_ * SP_ * (HID_ / 4);
    for (; idx < total; idx += gridDim.x * 256) {
        int k4 = idx & 31;
        int rest = idx >> 5;
        int s = rest % SP_;
        int b = rest / SP_;
        float4 v = make_float4(0.f, 0.f, 0.f, 0.f);
        if (s < S_) {
            int a = s % 49 + 1, t = s / 49;
            v = *(const float4*)&hin[(((b * A_ + a) * T_ + t) * HID_) + k4 * 4];
        }
        __nv_bfloat16 hx = __float2bfloat16(v.x), hy = __float2bfloat16(v.y);
        __nv_bfloat16 hz = __float2bfloat16(v.z), hw = __float2bfloat16(v.w);
        __nv_bfloat162 h01; h01.x = hx; h01.y = hy;
        __nv_bfloat162 h23; h23.x = hz; h23.y = hw;
        __nv_bfloat162 l01 = __floats2bfloat162_rn(v.x - __bfloat162float(hx),
                                                   v.y - __bfloat162float(hy));
        __nv_bfloat162 l23 = __floats2bfloat162_rn(v.z - __bfloat162float(hz),
                                                   v.w - __bfloat162float(hw));
        size_t off = ((size_t)(b * SP_ + s)) * HID_ + k4 * 4;
        *(uint2*)&g_Xhi[off] = make_uint2(*(uint32_t*)&h01, *(uint32_t*)&h23);
        *(uint2*)&g_Xlo[off] = make_uint2(*(uint32_t*)&l01, *(uint32_t*)&l23);
    }
}

// ---------------- a_dst + sort thresholds per (b,h) ------------------------
__global__ __launch_bounds__(64) void adst_sort_kernel(const float* __restrict__ hin) {
    __shared__ float hs[T_ * 129];
    __shared__ float vd[HID_];
    __shared__ float dv[64];
    __shared__ float eth[64];
    __shared__ int per[64];
    int h = blockIdx.x, b = blockIdx.y, tid = threadIdx.x;

    for (int i = tid; i < T_ * HID_; i += 64) {
        int t = i >> 7, d = i & 127;
        hs[t * 129 + d] = hin[(size_t)(b * A_) * T_ * HID_ + i];   // ego rows contiguous
    }
    for (int i = tid; i < HID_; i += 64) vd[i] = g_vdst[h * HID_ + i];
    __syncthreads();

    float dd = 0.f, key = __int_as_float(0x7f800000);
    if (tid < T_) {
        const float* hr = &hs[tid * 129];
        float a = 0.f;
        #pragma unroll 16
        for (int d = 0; d < HID_; d++) a += hr[d] * vd[d];
        dd = a;
        key = __expf(-a);
    }
    dv[tid] = dd; eth[tid] = key; per[tid] = tid;

    for (int k = 2; k <= 64; k <<= 1) {
        for (int j = k >> 1; j > 0; j >>= 1) {
            __syncthreads();
            int ixj = tid ^ j;
            if (ixj > tid) {
                float a = eth[tid], c2 = eth[ixj];
                bool up = ((tid & k) == 0);
                if (up ? (a > c2) : (a < c2)) {
                    eth[tid] = c2; eth[ixj] = a;
                    int p = per[tid]; per[tid] = per[ixj]; per[ixj] = p;
                }
            }
        }
    }
    __syncthreads();

    g_eth[(b * H_ + h) * 64 + tid] = eth[tid];
    if (tid < T_) {
        float d2 = dv[per[tid]];
        int o = (b * H_ + h) * T_ + tid;
        g_e1[o] = __expf(d2);
        g_e2[o] = __expf(NEG_SLOPE * d2);
        g_perm[o] = per[tid];
    }
}

// ---------------- fused GEMM + bucket accumulation + output fill -----------
// grid (8 head-blocks, 2 s-partitions, 32 b); CTA: 4 heads (N=64), M=64, ~20 tiles.
__global__ __launch_bounds__(256, 2) void fused_kernel(float* __restrict__ gout,
                                                       const float* __restrict__ bias,
                                                       const float* __restrict__ att_src) {
    extern __shared__ char sm[];
    uint32_t sbase = smem_u32(sm);
    int tid = threadIdx.x, wid = tid >> 5, lane = tid & 31;
    int nb = blockIdx.x, part = blockIdx.y, b = blockIdx.z;
    int n0 = nb * 64, h0 = nb * 4;
    int rev = (nb + part + b) & 1;         // decorrelate co-resident CTA phases
    int t0 = part * 20, t1 = part ? NT : 20;
    int NTL = t1 - t0;                     // 20 or 19

    // ---- fill output with broadcast bias (fire-and-forget STG prologue) ----
    {
        int idx4 = (((b * NPART + part) * 8) + nb) * 256 + tid;   // 0..131071
        float4 bv = ((const float4*)bias)[idx4 & 127];
        float4* o4 = (float4*)gout;
        for (int p = idx4; p < OUT4; p += 131072) o4[p] = bv;
    }

    // ---- resident W (bf16 hi/lo), att_src, thresholds; zero buckets ----
    #pragma unroll
    for (int i = 0; i < 4; i++) {
        int slot = tid + 256 * i;          // 1024 slots = 64 rows x 16 k8
        int row = slot >> 4, k8 = slot & 15;
        size_t off = (size_t)(row * ASTR + k8 * 8) * 2;
        *(uint4*)(sm + FB_WHI + off) = *(const uint4*)&g_Whi[(n0 + row) * HID_ + k8 * 8];
        *(uint4*)(sm + FB_WLO + off) = *(const uint4*)&g_Wlo[(n0 + row) * HID_ + k8 * 8];
    }
    if (tid < 64) ((float*)(sm + FB_ASC))[tid] = att_src[h0 * 16 + tid];
    ((float*)(sm + FB_ETH))[tid] = g_eth[(b * H_ + h0) * 64 + tid];
    for (int i = tid; i < (27136 + 1696) / 4; i += 256)
        ((float*)(sm + FB_BKT))[i] = 0.f;
    __syncthreads();                       // ASC/ETH visible for reg preload

    int wm = wid & 3, wn = wid >> 2;       // m block 16 rows, n block 32 cols
    int at = lane >> 2, kq = (lane & 3) * 2;

    // ---- preload att_src values this thread needs (step1-from-regs) ----
    float ascv[4][2];
    #pragma unroll
    for (int nt = 0; nt < 4; nt++) {
        ascv[nt][0] = ((const float*)(sm + FB_ASC))[wn * 32 + nt * 8 + kq];
        ascv[nt][1] = ((const float*)(sm + FB_ASC))[wn * 32 + nt * 8 + kq + 1];
    }

    // ---- ldmatrix lane addresses (constant across tiles; +32B per ks) ----
    int g8 = lane >> 3, l8 = lane & 7;
    uint32_t aAddrHi = sbase + FB_AHI +
        ((uint32_t)((wm * 16 + (g8 & 1) * 8 + l8) * ASTR + (g8 >> 1) * 8)) * 2;
    uint32_t aAddrLo = aAddrHi + (FB_ALO - FB_AHI);
    uint32_t bAddrHi0 = sbase + FB_WHI +
        ((uint32_t)((wn * 32 + (g8 >> 1) * 8 + l8) * ASTR + (g8 & 1) * 8)) * 2;
    uint32_t bAddrHi1 = bAddrHi0 + 16 * ASTR * 2;
    uint32_t bAddrLo0 = bAddrHi0 + (FB_WLO - FB_WHI);
    uint32_t bAddrLo1 = bAddrHi1 + (FB_WLO - FB_WHI);

    // ---- step2 constants: warps 0-3; lanes 0-15 arr0, 16-31 arr1 ----
    int s2hl = wid;                        // head (warps 0-3 only)
    int s2arr = lane >> 4, s2c = lane & 15;
    bool s2doQ = (s2c == 0);

    const __nv_bfloat16* xhiBase = g_Xhi + (size_t)b * SP_ * HID_;
    const __nv_bfloat16* xloBase = g_Xlo + (size_t)b * SP_ * HID_;

    // per-thread copy slots: 4 rows of A (row = (tid+256i)>>4, k8 = &15)
    int cpRow = tid >> 4, cpK8 = tid & 15;
    uint32_t cpDstHi = sbase + FB_AHI + (uint32_t)(cpRow * ASTR + cpK8 * 8) * 2;
    uint32_t cpDstLo = cpDstHi + (FB_ALO - FB_AHI);

    // ---- prefetch A_lo for first tile ----
    {
        int tl0 = rev ? (t1 - 1) : t0;
        #pragma unroll
        for (int i = 0; i < 4; i++) {
            int row = cpRow + i * 16;
            CP_ASYNC16(cpDstLo + (uint32_t)(i * 16 * ASTR * 2),
                       (const char*)(xloBase + (size_t)(tl0 * 64 + row) * HID_ + cpK8 * 8));
        }
        CP_COMMIT();
    }

    for (int tile = 0; tile < NTL; tile++) {
        int tl = rev ? (t1 - 1 - tile) : (t0 + tile);
        int s0 = tl * 64;
        __syncthreads();   // step2(t-1) done with outs (A_hi region)

        // ---- copy A_hi(tile) via cp.async; wait for it + earlier lo ----
        #pragma unroll
        for (int i = 0; i < 4; i++) {
            int row = cpRow + i * 16;
            CP_ASYNC16(cpDstHi + (uint32_t)(i * 16 * ASTR * 2),
                       (const char*)(xhiBase + (size_t)(s0 + row) * HID_ + cpK8 * 8));
        }
        CP_COMMIT();
        CP_WAIT0();
        __syncthreads();

        // ---- MMA mainloop: warp tile 16(m) x 32(n), ldmatrix frags ----
        float accA[4][4], accB[4][4];      // hi*hi ; hi*lo + lo*hi
        #pragma unroll
        for (int nt = 0; nt < 4; nt++)
            #pragma unroll
            for (int j = 0; j < 4; j++) { accA[nt][j] = 0.f; accB[nt][j] = 0.f; }

        #pragma unroll
        for (int ks = 0; ks < 8; ks++) {
            uint32_t ko = ks * 32;         // 16 bf16 = 32 bytes per k-step
            uint32_t ah[4], al[4], bh[4][2], bl[4][2];
            LDMX4(ah[0], ah[1], ah[2], ah[3], aAddrHi + ko);
            LDMX4(al[0], al[1], al[2], al[3], aAddrLo + ko);
            LDMX4(bh[0][0], bh[0][1], bh[1][0], bh[1][1], bAddrHi0 + ko);
            LDMX4(bh[2][0], bh[2][1], bh[3][0], bh[3][1], bAddrHi1 + ko);
            LDMX4(bl[0][0], bl[0][1], bl[1][0], bl[1][1], bAddrLo0 + ko);
            LDMX4(bl[2][0], bl[2][1], bl[3][0], bl[3][1], bAddrLo1 + ko);
            #pragma unroll
            for (int nt = 0; nt < 4; nt++) {
                mma_bf16(accA[nt], ah, bh[nt]);
                mma_bf16(accB[nt], ah, bl[nt]);
                mma_bf16(accB[nt], al, bh[nt]);
            }
        }
        __syncthreads();    // done reading A_hi/A_lo

        // ---- prefetch next tile's A_lo (A_lo free now; overlaps step1/2) ----
        {
            int tlN = rev ? (tl - 1) : (tl + 1);
            if (tlN >= t0 && tlN < t1) {
                #pragma unroll
                for (int i = 0; i < 4; i++) {
                    int row = cpRow + i * 16;
                    CP_ASYNC16(cpDstLo + (uint32_t)(i * 16 * ASTR * 2),
                               (const char*)(xloBase + (size_t)(tlN * 64 + row) * HID_ + cpK8 * 8));
                }
                CP_COMMIT();
            }
        }

        // ---- stage D (summed) + step1 from registers ----
        float* outs = (float*)(sm + FB_OUTS);
        float sum0[4], sum1[4], sum2[4], sum3[4];
        {
            int r = wm * 16 + at;
            #pragma unroll
            for (int nt = 0; nt < 4; nt++) {
                sum0[nt] = accA[nt][0] + accB[nt][0];
                sum1[nt] = accA[nt][1] + accB[nt][1];
                sum2[nt] = accA[nt][2] + accB[nt][2];
                sum3[nt] = accA[nt][3] + accB[nt][3];
                int cc = wn * 32 + nt * 8 + kq;
                *(float2*)&outs[r * OSTR + cc]       = make_float2(sum0[nt], sum1[nt]);
                *(float2*)&outs[(r + 8) * OSTR + cc] = make_float2(sum2[nt], sum3[nt]);
            }
        }
        {
            // partial a_src dots from registers
            float dA = sum0[0] * ascv[0][0] + sum1[0] * ascv[0][1]
                     + sum0[1] * ascv[1][0] + sum1[1] * ascv[1][1];   // (r, h0)
            float dB = sum0[2] * ascv[2][0] + sum1[2] * ascv[2][1]
                     + sum0[3] * ascv[3][0] + sum1[3] * ascv[3][1];   // (r, h1)
            float dC = sum2[0] * ascv[0][0] + sum3[0] * ascv[0][1]
                     + sum2[1] * ascv[1][0] + sum3[1] * ascv[1][1];   // (r+8, h0)
            float dD = sum2[2] * ascv[2][0] + sum3[2] * ascv[2][1]
                     + sum2[3] * ascv[3][0] + sum3[3] * ascv[3][1];   // (r+8, h1)
            dA += __shfl_xor_sync(0xffffffffu, dA, 1);
            dA += __shfl_xor_sync(0xffffffffu, dA, 2);
            dB += __shfl_xor_sync(0xffffffffu, dB, 1);
            dB += __shfl_xor_sync(0xffffffffu, dB, 2);
            dC += __shfl_xor_sync(0xffffffffu, dC, 1);
            dC += __shfl_xor_sync(0xffffffffu, dC, 2);
            dD += __shfl_xor_sync(0xffffffffu, dD, 1);
            dD += __shfl_xor_sync(0xffffffffu, dD, 2);
            int sel = lane & 3;
            float dot = (sel == 0) ? dA : (sel == 1) ? dB : (sel == 2) ? dC : dD;
            int srow = wm * 16 + at + (sel >> 1) * 8;
            int hl = 2 * wn + (sel & 1);
            float v1 = 0.f, v2 = 0.f;
            int r = 0;
            if (s0 + srow < S_) {
                v1 = __expf(dot);
                v2 = __expf(NEG_SLOPE * dot);
                const float* e = (const float*)(sm + FB_ETH) + hl * 64;
                if (e[r + 31] < v1) r += 32;
                if (e[r + 15] < v1) r += 16;
                if (e[r + 7]  < v1) r += 8;
                if (e[r + 3]  < v1) r += 4;
                if (e[r + 1]  < v1) r += 2;
                if (e[r]      < v1) r += 1;
            }
            float* qs1 = (float*)(sm + FB_QS1);
            float* qs2 = (float*)(sm + FB_QS2);
            int*   rox = (int*)(sm + FB_RO);
            qs1[hl * 64 + srow] = v1;
            qs2[hl * 64 + srow] = v2;
            rox[hl * 64 + srow] = r * 16;
        }
        __syncthreads();

        // ---- step2 merged: warps 0-3; lanes 0-15 arr0(q1), 16-31 arr1(q2) ----
        if (wid < 4) {
            float* qs1 = (float*)(sm + FB_QS1);
            float* qs2 = (float*)(sm + FB_QS2);
            int*   rox = (int*)(sm + FB_RO);
            const float* qarr = (s2arr ? qs2 : qs1) + s2hl * 64;
            const int* rop = rox + s2hl * 64;
            const float* ox = outs + s2hl * 16 + s2c;
            float* bk = (float*)(sm + FB_BKT) + (s2hl * 2 + s2arr) * 848 + s2c;
            float* qb = (float*)(sm + FB_QBK) + (s2hl * 2 + s2arr) * 53;
            for (int g = 0; g < 16; g++) {
                int s4 = g * 4;
                int4 r4 = *(const int4*)(rop + s4);
                float4 q4 = *(const float4*)(qarr + s4);
                float x0 = ox[(s4 + 0) * OSTR], x1 = ox[(s4 + 1) * OSTR];
                float x2 = ox[(s4 + 2) * OSTR], x3 = ox[(s4 + 3) * OSTR];
                int r0 = r4.x, r1 = r4.y, r2 = r4.z, r3 = r4.w;
                float v0 = q4.x * x0, v1 = q4.y * x1, v2 = q4.z * x2, v3 = q4.w * x3;
                float w0 = q4.x, w1 = q4.y, w2 = q4.z, w3 = q4.w;
                if (r1 == r0) { v0 += v1; w0 += w1; r1 = TRASH; v1 = 0.f; w1 = 0.f; }
                if (r2 == r0) { v0 += v2; w0 += w2; r2 = TRASH; v2 = 0.f; w2 = 0.f; }
                else if (r2 == r1) { v1 += v2; w1 += w2; r2 = TRASH; v2 = 0.f; w2 = 0.f; }
                if (r3 == r0) { v0 += v3; w0 += w3; r3 = TRASH; v3 = 0.f; w3 = 0.f; }
                else if (r3 == r1) { v1 += v3; w1 += w3; r3 = TRASH; v3 = 0.f; w3 = 0.f; }
                else if (r3 == r2) { v2 += v3; w2 += w3; r3 = TRASH; v3 = 0.f; w3 = 0.f; }
                float b0 = bk[r0], b1 = bk[r1], b2 = bk[r2], b3 = bk[r3];
                bk[r0] = b0 + v0; bk[r1] = b1 + v1; bk[r2] = b2 + v2; bk[r3] = b3 + v3;
                if (s2doQ) {
                    float c0 = qb[r0 >> 4], c1 = qb[r1 >> 4];
                    float c2 = qb[r2 >> 4], c3 = qb[r3 >> 4];
                    qb[r0 >> 4] = c0 + w0; qb[r1 >> 4] = c1 + w1;
                    qb[r2 >> 4] = c2 + w2; qb[r3 >> 4] = c3 + w3;
                }
            }
        }
    }
    __syncthreads();

    // ---- write bucket partials to global (per s-partition) ----
    const float* bks = (const float*)(sm + FB_BKT);
    for (int i = tid; i < 4 * 2 * NB * 16; i += 256) {
        int c = i & 15;
        int hr = i >> 4;                    // hl*102 + arr*51 + r
        int hl = hr / 102, rem = hr % 102;
        int arr = rem / NB, r = rem % NB;
        g_bkt[((((size_t)(b * H_ + h0 + hl) * NPART + part) * 2 + arr) * NB + r) * 16 + c] =
            bks[(hl * 2 + arr) * 848 + r * 16 + c];
    }
    const float* qbs = (const float*)(sm + FB_QBK);
    for (int i = tid; i < 4 * 2 * NB; i += 256) {
        int hl = i / (2 * NB), rem = i % (2 * NB);
        int arr = rem / NB, r = rem % NB;
        g_qbk[(((b * H_ + h0 + hl) * NPART + part) * 2 + arr) * NB + r] =
            qbs[(hl * 2 + arr) * 53 + r];
    }
}

// ---------------- finish: sum partials, scans + Z + output ------------------
__global__ __launch_bounds__(64) void finish_kernel(float* __restrict__ out,
                                                    const float* __restrict__ bias) {
    __shared__ float BS[2 * NB * 16];
    __shared__ float QS[2 * NB];
    __shared__ float e1s[T_], e2s[T_], Zs[T_];
    __shared__ int per[T_];
    int h = blockIdx.x, b = blockIdx.y, tid = threadIdx.x;

    const float* gb = g_bkt + (size_t)(b * H_ + h) * NPART * 2 * NB * 16;
    for (int i = tid; i < 2 * NB * 16; i += 64)
        BS[i] = gb[i] + gb[2 * NB * 16 + i];
    const float* gq = g_qbk + (b * H_ + h) * NPART * 2 * NB;
    for (int i = tid; i < 2 * NB; i += 64)
        QS[i] = gq[i] + gq[2 * NB + i];
    if (tid < T_) {
        int o = (b * H_ + h) * T_ + tid;
        e1s[tid] = g_e1[o];
        e2s[tid] = g_e2[o];
        per[tid] = g_perm[o];
    }
    __syncthreads();

    if (tid < 32) {
        int arr = tid >> 4, c = tid & 15;
        float run = 0.f;
        if (arr == 0) {
            for (int r = NB - 1; r >= 0; r--) { run += BS[r * 16 + c]; BS[r * 16 + c] = run; }
        } else {
            for (int r = 0; r < NB; r++) { run += BS[(NB + r) * 16 + c]; BS[(NB + r) * 16 + c] = run; }
        }
    } else if (tid < 34) {
        int arr = tid - 32;
        float run = 0.f;
        if (arr == 0) {
            for (int r = NB - 1; r >= 0; r--) { run += QS[r]; QS[r] = run; }
        } else {
            for (int r = 0; r < NB; r++) { run += QS[NB + r]; QS[NB + r] = run; }
        }
    }
    __syncthreads();

    if (tid < T_)
        Zs[tid] = 1.0f / (e1s[tid] * QS[tid + 1] + e2s[tid] * QS[NB + tid]);
    __syncthreads();

    for (int i = tid; i < T_ * 16; i += 64) {
        int si = i >> 4, c = i & 15;
        int t = per[si];
        float o = Zs[si] * (e1s[si] * BS[(si + 1) * 16 + c] + e2s[si] * BS[(NB + si) * 16 + c]);
        out[((size_t)(b * A_) * T_ + t) * HC_ + h * C_ + c] = o + bias[h * C_ + c];
    }
}

// ---------------------------------------------------------------------------
extern "C" void kernel_launch(void* const* d_in, const int* in_sizes, int n_in,
                              void* d_out, int out_size) {
    const float* hin     = (const float*)d_in[0];
    const float* W       = (const float*)d_in[1];
    const float* att_src = (const float*)d_in[2];
    const float* att_dst = (const float*)d_in[3];
    const float* bias    = (const float*)d_in[4];
    float* out = (float*)d_out;

    cudaFuncSetAttribute(fused_kernel, cudaFuncAttributeMaxDynamicSharedMemorySize, SMEM_FUSED);

    prep_kernel<<<(HID_ * HC_ + 255) / 256, 256>>>(W, att_dst);

    xprep_kernel<<<4096, 256>>>(hin);

    dim3 gs(H_, B_);
    adst_sort_kernel<<<gs, 64>>>(hin);

    dim3 gf(8, NPART, B_);
    fused_kernel<<<gf, 256, SMEM_FUSED>>>(out, bias, att_src);

    finish_kernel<<<gs, 64>>>(out, bias);
}

// round 14
// speedup vs baseline: 1.3364x; 1.3364x over previous
#include <cuda_runtime.h>
#include <cuda_bf16.h>
#include <cstdint>

#define A_   50
#define T_   50
#define HID_ 128
#define H_   32
#define C_   16
#define B_   32
#define S_   2450          // T_*(A_-1)
#define SP_  2496          // S_ padded to 64
#define HC_  512           // H_*C_
#define NEG_SLOPE 0.2f
#define NB   51            // buckets 0..50
#define OUT4 10240000      // total float4 in output

// ---------------- scratch (device globals; no allocations allowed) --------
__device__ float g_vdst[H_ * HID_];                         // [h][d]
__device__ __align__(16) __nv_bfloat16 g_Whi[HC_ * HID_];   // [n][k]
__device__ __align__(16) __nv_bfloat16 g_Wlo[HC_ * HID_];   // [n][k]
__device__ __align__(16) __nv_bfloat16 g_Xhi[(size_t)B_ * SP_ * HID_];  // 20.4 MB
__device__ __align__(16) __nv_bfloat16 g_Xlo[(size_t)B_ * SP_ * HID_];
__device__ float g_eth[B_ * H_ * 64];                       // sorted thresholds (+INF pad)
__device__ float g_e1[B_ * H_ * T_];
__device__ float g_e2[B_ * H_ * T_];
__device__ int   g_perm[B_ * H_ * T_];
__device__ __align__(16) float g_bkt[(size_t)B_ * H_ * 2 * NB * 16];  // 6.7 MB
__device__ float g_qbk[B_ * H_ * 2 * NB];

__device__ __forceinline__ uint32_t smem_u32(const void* p) {
    uint32_t a;
    asm("{ .reg .u64 t; cvta.to.shared.u64 t, %1; cvt.u32.u64 %0, t; }" : "=r"(a) : "l"(p));
    return a;
}

// mma.sync m16n8k16 row.col f32.bf16.bf16.f32
__device__ __forceinline__ void mma_bf16(float* c, const uint32_t* a, const uint32_t* b) {
    asm volatile(
        "mma.sync.aligned.m16n8k16.row.col.f32.bf16.bf16.f32 "
        "{%0,%1,%2,%3}, {%4,%5,%6,%7}, {%8,%9}, {%0,%1,%2,%3};"
        : "+f"(c[0]), "+f"(c[1]), "+f"(c[2]), "+f"(c[3])
        : "r"(a[0]), "r"(a[1]), "r"(a[2]), "r"(a[3]), "r"(b[0]), "r"(b[1]));
}

#define LDMX4(r0, r1, r2, r3, addr) \
    asm volatile("ldmatrix.sync.aligned.m8n8.x4.shared.b16 {%0,%1,%2,%3}, [%4];" \
        : "=r"(r0), "=r"(r1), "=r"(r2), "=r"(r3) : "r"(addr))

#define CP_ASYNC16(dst, src) \
    asm volatile("cp.async.ca.shared.global [%0], [%1], 16;" :: "r"(dst), "l"(src))
#define CP_COMMIT() asm volatile("cp.async.commit_group;")
#define CP_WAIT0()  asm volatile("cp.async.wait_group 0;" ::: "memory")

// ---- fused kernel smem layout (bytes); M=64 rows, 4 heads (N=64) ----
#define ASTR   136
#define OSTR   68
#define NT     39                      // SP_/64
#define FB_WHI  0                      // 17408
#define FB_WLO  17408                  // 17408
#define FB_AHI  34816                  // 17408
#define FB_ALO  52224                  // 17408
#define FB_OUTS FB_AHI                 // outs aliases A_hi ONLY (A_lo stays live)
#define FB_BKT  69632                  // 4h*2arr*53*16*4 = 27136
#define FB_QBK  96768                  // 4*2*53*4 = 1696
#define FB_ETH  98464                  // 4*64*4 = 1024
#define FB_ASC  99488                  // 4*16*4 = 256
#define FB_QS1  99744                  // 4*64*4
#define FB_QS2  100768
#define FB_RO   101792
#define SMEM_FUSED 102816
#define TRASH  816                     // row 51 within a (hl,arr) region (53 rows)

// ---------------- prep: bf16-split W, contract att_dst into v_dst ----------
__global__ void prep_kernel(const float* __restrict__ W,
                            const float* __restrict__ att_dst) {
    int idx = blockIdx.x * blockDim.x + threadIdx.x;
    if (idx < HID_ * HC_) {
        float w = W[idx];
        __nv_bfloat16 hi = __float2bfloat16(w);
        g_Whi[idx] = hi;
        g_Wlo[idx] = __float2bfloat16(w - __bfloat162float(hi));
    }
    if (idx < H_ * HID_) {
        int h = idx / HID_, d = idx % HID_;
        float s2 = 0.f;
        #pragma unroll
        for (int c = 0; c < C_; c++)
            s2 += W[(h * C_ + c) * HID_ + d] * att_dst[h * C_ + c];
        g_vdst[idx] = s2;
    }
}

// ---------------- xprep: split X rows (non-ego, s-indexed) to bf16 hi/lo ---
__global__ __launch_bounds__(256) void xprep_kernel(const float* __restrict__ hin) {
    int idx = blockIdx.x * 256 + threadIdx.x;          // one float4 (4 k) per iter
    const int total = B_ * SP_ * (HID_ / 4);
    for (; idx < total; idx += gridDim.x * 256) {
        int k4 = idx & 31;
        int rest = idx >> 5;
        int s = rest % SP_;
        int b = rest / SP_;
        float4 v = make_float4(0.f, 0.f, 0.f, 0.f);
        if (s < S_) {
            int a = s % 49 + 1, t = s / 49;
            v = *(const float4*)&hin[(((b * A_ + a) * T_ + t) * HID_) + k4 * 4];
        }
        __nv_bfloat16 hx = __float2bfloat16(v.x), hy = __float2bfloat16(v.y);
        __nv_bfloat16 hz = __float2bfloat16(v.z), hw = __float2bfloat16(v.w);
        __nv_bfloat162 h01; h01.x = hx; h01.y = hy;
        __nv_bfloat162 h23; h23.x = hz; h23.y = hw;
        __nv_bfloat162 l01 = __floats2bfloat162_rn(v.x - __bfloat162float(hx),
                                                   v.y - __bfloat162float(hy));
        __nv_bfloat162 l23 = __floats2bfloat162_rn(v.z - __bfloat162float(hz),
                                                   v.w - __bfloat162float(hw));
        size_t off = ((size_t)(b * SP_ + s)) * HID_ + k4 * 4;
        *(uint2*)&g_Xhi[off] = make_uint2(*(uint32_t*)&h01, *(uint32_t*)&h23);
        *(uint2*)&g_Xlo[off] = make_uint2(*(uint32_t*)&l01, *(uint32_t*)&l23);
    }
}

// ---------------- a_dst + sort thresholds per (b,h) ------------------------
__global__ __launch_bounds__(64) void adst_sort_kernel(const float* __restrict__ hin) {
    __shared__ float hs[T_ * 129];
    __shared__ float vd[HID_];
    __shared__ float dv[64];
    __shared__ float eth[64];
    __shared__ int per[64];
    int h = blockIdx.x, b = blockIdx.y, tid = threadIdx.x;

    for (int i = tid; i < T_ * HID_; i += 64) {
        int t = i >> 7, d = i & 127;
        hs[t * 129 + d] = hin[(size_t)(b * A_) * T_ * HID_ + i];   // ego rows contiguous
    }
    for (int i = tid; i < HID_; i += 64) vd[i] = g_vdst[h * HID_ + i];
    __syncthreads();

    float dd = 0.f, key = __int_as_float(0x7f800000);
    if (tid < T_) {
        const float* hr = &hs[tid * 129];
        float a = 0.f;
        #pragma unroll 16
        for (int d = 0; d < HID_; d++) a += hr[d] * vd[d];
        dd = a;
        key = __expf(-a);
    }
    dv[tid] = dd; eth[tid] = key; per[tid] = tid;

    for (int k = 2; k <= 64; k <<= 1) {
        for (int j = k >> 1; j > 0; j >>= 1) {
            __syncthreads();
            int ixj = tid ^ j;
            if (ixj > tid) {
                float a = eth[tid], c2 = eth[ixj];
                bool up = ((tid & k) == 0);
                if (up ? (a > c2) : (a < c2)) {
                    eth[tid] = c2; eth[ixj] = a;
                    int p = per[tid]; per[tid] = per[ixj]; per[ixj] = p;
                }
            }
        }
    }
    __syncthreads();

    g_eth[(b * H_ + h) * 64 + tid] = eth[tid];
    if (tid < T_) {
        float d2 = dv[per[tid]];
        int o = (b * H_ + h) * T_ + tid;
        g_e1[o] = __expf(d2);
        g_e2[o] = __expf(NEG_SLOPE * d2);
        g_perm[o] = per[tid];
    }
}

// ---------------- fused GEMM + bucket accumulation + output fill -----------
// grid (8 head-blocks, 32 b); CTA owns 4 heads (N=64), M=64 rows, 39 tiles.
__global__ __launch_bounds__(256, 2) void fused_kernel(float* __restrict__ gout,
                                                       const float* __restrict__ bias,
                                                       const float* __restrict__ att_src) {
    extern __shared__ char sm[];
    uint32_t sbase = smem_u32(sm);
    int tid = threadIdx.x, wid = tid >> 5, lane = tid & 31;
    int nb = blockIdx.x, b = blockIdx.y;
    int n0 = nb * 64, h0 = nb * 4;
    int rev = (nb + b) & 1;                // decorrelate co-resident CTA phases

    // ---- fill output with broadcast bias (fire-and-forget STG prologue) ----
    {
        int idx4 = (b * 8 + nb) * 256 + tid;          // 0..65535
        float4 bv = ((const float4*)bias)[idx4 & 127];
        float4* o4 = (float4*)gout;
        for (int p = idx4; p < OUT4; p += 65536) o4[p] = bv;
    }

    // ---- resident W (bf16 hi/lo), att_src, thresholds; zero buckets ----
    #pragma unroll
    for (int i = 0; i < 4; i++) {
        int slot = tid + 256 * i;          // 1024 slots = 64 rows x 16 k8
        int row = slot >> 4, k8 = slot & 15;
        size_t off = (size_t)(row * ASTR + k8 * 8) * 2;
        *(uint4*)(sm + FB_WHI + off) = *(const uint4*)&g_Whi[(n0 + row) * HID_ + k8 * 8];
        *(uint4*)(sm + FB_WLO + off) = *(const uint4*)&g_Wlo[(n0 + row) * HID_ + k8 * 8];
    }
    if (tid < 64) ((float*)(sm + FB_ASC))[tid] = att_src[h0 * 16 + tid];
    ((float*)(sm + FB_ETH))[tid] = g_eth[(b * H_ + h0) * 64 + tid];
    for (int i = tid; i < (27136 + 1696) / 4; i += 256)
        ((float*)(sm + FB_BKT))[i] = 0.f;
    __syncthreads();                       // ASC/ETH visible for reg preload

    int wm = wid & 3, wn = wid >> 2;       // m block 16 rows, n block 32 cols
    int at = lane >> 2, kq = (lane & 3) * 2;

    // ---- preload att_src values this thread needs (step1-from-regs) ----
    float ascv[4][2];
    #pragma unroll
    for (int nt = 0; nt < 4; nt++) {
        ascv[nt][0] = ((const float*)(sm + FB_ASC))[wn * 32 + nt * 8 + kq];
        ascv[nt][1] = ((const float*)(sm + FB_ASC))[wn * 32 + nt * 8 + kq + 1];
    }

    // ---- ldmatrix lane addresses (constant across tiles; +32B per ks) ----
    int g8 = lane >> 3, l8 = lane & 7;
    uint32_t aAddrHi = sbase + FB_AHI +
        ((uint32_t)((wm * 16 + (g8 & 1) * 8 + l8) * ASTR + (g8 >> 1) * 8)) * 2;
    uint32_t aAddrLo = aAddrHi + (FB_ALO - FB_AHI);
    uint32_t bAddrHi0 = sbase + FB_WHI +
        ((uint32_t)((wn * 32 + (g8 >> 1) * 8 + l8) * ASTR + (g8 & 1) * 8)) * 2;
    uint32_t bAddrHi1 = bAddrHi0 + 16 * ASTR * 2;
    uint32_t bAddrLo0 = bAddrHi0 + (FB_WLO - FB_WHI);
    uint32_t bAddrLo1 = bAddrHi1 + (FB_WLO - FB_WHI);

    // ---- step2 constants: warp = (head, arr); lanes 0-15 B, lane 16 Q ----
    int s2hl = wid >> 1, s2arr = wid & 1;
    int s2c = lane & 15;
    bool s2doB = (lane < 16), s2doQ = (lane == 16);

    const __nv_bfloat16* xhiBase = g_Xhi + (size_t)b * SP_ * HID_;
    const __nv_bfloat16* xloBase = g_Xlo + (size_t)b * SP_ * HID_;

    // per-thread copy slots: 4 rows of A (row = (tid+256i)>>4, k8 = &15)
    int cpRow = tid >> 4, cpK8 = tid & 15;
    uint32_t cpDstHi = sbase + FB_AHI + (uint32_t)(cpRow * ASTR + cpK8 * 8) * 2;
    uint32_t cpDstLo = cpDstHi + (FB_ALO - FB_AHI);

    // ---- prefetch A_lo for first tile ----
    {
        int tl0 = rev ? (NT - 1) : 0;
        #pragma unroll
        for (int i = 0; i < 4; i++) {
            int row = cpRow + i * 16;
            CP_ASYNC16(cpDstLo + (uint32_t)(i * 16 * ASTR * 2),
                       (const char*)(xloBase + (size_t)(tl0 * 64 + row) * HID_ + cpK8 * 8));
        }
        CP_COMMIT();
    }

    for (int tile = 0; tile < NT; tile++) {
        int tl = rev ? (NT - 1 - tile) : tile;
        int s0 = tl * 64;
        __syncthreads();   // step2(t-1) done with outs (A_hi region)

        // ---- copy A_hi(tile) via cp.async; wait for it + earlier lo ----
        #pragma unroll
        for (int i = 0; i < 4; i++) {
            int row = cpRow + i * 16;
            CP_ASYNC16(cpDstHi + (uint32_t)(i * 16 * ASTR * 2),
                       (const char*)(xhiBase + (size_t)(s0 + row) * HID_ + cpK8 * 8));
        }
        CP_COMMIT();
        CP_WAIT0();
        __syncthreads();

        // ---- MMA mainloop: warp tile 16(m) x 32(n), ldmatrix frags ----
        float accA[4][4], accB[4][4];      // hi*hi ; hi*lo + lo*hi
        #pragma unroll
        for (int nt = 0; nt < 4; nt++)
            #pragma unroll
            for (int j = 0; j < 4; j++) { accA[nt][j] = 0.f; accB[nt][j] = 0.f; }

        #pragma unroll
        for (int ks = 0; ks < 8; ks++) {
            uint32_t ko = ks * 32;         // 16 bf16 = 32 bytes per k-step
            uint32_t ah[4], al[4], bh[4][2], bl[4][2];
            LDMX4(ah[0], ah[1], ah[2], ah[3], aAddrHi + ko);
            LDMX4(al[0], al[1], al[2], al[3], aAddrLo + ko);
            LDMX4(bh[0][0], bh[0][1], bh[1][0], bh[1][1], bAddrHi0 + ko);
            LDMX4(bh[2][0], bh[2][1], bh[3][0], bh[3][1], bAddrHi1 + ko);
            LDMX4(bl[0][0], bl[0][1], bl[1][0], bl[1][1], bAddrLo0 + ko);
            LDMX4(bl[2][0], bl[2][1], bl[3][0], bl[3][1], bAddrLo1 + ko);
            #pragma unroll
            for (int nt = 0; nt < 4; nt++) {
                mma_bf16(accA[nt], ah, bh[nt]);
                mma_bf16(accB[nt], ah, bl[nt]);
                mma_bf16(accB[nt], al, bh[nt]);
            }
        }
        __syncthreads();    // done reading A_hi/A_lo

        // ---- prefetch next tile's A_lo (A_lo free now; overlaps step1/2) ----
        {
            int tlN = rev ? (tl - 1) : (tl + 1);
            if (tlN >= 0 && tlN < NT) {
                #pragma unroll
                for (int i = 0; i < 4; i++) {
                    int row = cpRow + i * 16;
                    CP_ASYNC16(cpDstLo + (uint32_t)(i * 16 * ASTR * 2),
                               (const char*)(xloBase + (size_t)(tlN * 64 + row) * HID_ + cpK8 * 8));
                }
                CP_COMMIT();
            }
        }

        // ---- stage D (summed) + step1 from registers ----
        float* outs = (float*)(sm + FB_OUTS);
        float sum0[4], sum1[4], sum2[4], sum3[4];
        {
            int r = wm * 16 + at;
            #pragma unroll
            for (int nt = 0; nt < 4; nt++) {
                sum0[nt] = accA[nt][0] + accB[nt][0];
                sum1[nt] = accA[nt][1] + accB[nt][1];
                sum2[nt] = accA[nt][2] + accB[nt][2];
                sum3[nt] = accA[nt][3] + accB[nt][3];
                int cc = wn * 32 + nt * 8 + kq;
                *(float2*)&outs[r * OSTR + cc]       = make_float2(sum0[nt], sum1[nt]);
                *(float2*)&outs[(r + 8) * OSTR + cc] = make_float2(sum2[nt], sum3[nt]);
            }
        }
        {
            // partial a_src dots from registers
            float dA = sum0[0] * ascv[0][0] + sum1[0] * ascv[0][1]
                     + sum0[1] * ascv[1][0] + sum1[1] * ascv[1][1];   // (r, h0)
            float dB = sum0[2] * ascv[2][0] + sum1[2] * ascv[2][1]
                     + sum0[3] * ascv[3][0] + sum1[3] * ascv[3][1];   // (r, h1)
            float dC = sum2[0] * ascv[0][0] + sum3[0] * ascv[0][1]
                     + sum2[1] * ascv[1][0] + sum3[1] * ascv[1][1];   // (r+8, h0)
            float dD = sum2[2] * ascv[2][0] + sum3[2] * ascv[2][1]
                     + sum2[3] * ascv[3][0] + sum3[3] * ascv[3][1];   // (r+8, h1)
            dA += __shfl_xor_sync(0xffffffffu, dA, 1);
            dA += __shfl_xor_sync(0xffffffffu, dA, 2);
            dB += __shfl_xor_sync(0xffffffffu, dB, 1);
            dB += __shfl_xor_sync(0xffffffffu, dB, 2);
            dC += __shfl_xor_sync(0xffffffffu, dC, 1);
            dC += __shfl_xor_sync(0xffffffffu, dC, 2);
            dD += __shfl_xor_sync(0xffffffffu, dD, 1);
            dD += __shfl_xor_sync(0xffffffffu, dD, 2);
            int sel = lane & 3;
            float dot = (sel == 0) ? dA : (sel == 1) ? dB : (sel == 2) ? dC : dD;
            int srow = wm * 16 + at + (sel >> 1) * 8;
            int hl = 2 * wn + (sel & 1);
            float v1 = 0.f, v2 = 0.f;
            int r = 0;
            if (s0 + srow < S_) {
                v1 = __expf(dot);
                v2 = __expf(NEG_SLOPE * dot);
                const float* e = (const float*)(sm + FB_ETH) + hl * 64;
                if (e[r + 31] < v1) r += 32;
                if (e[r + 15] < v1) r += 16;
                if (e[r + 7]  < v1) r += 8;
                if (e[r + 3]  < v1) r += 4;
                if (e[r + 1]  < v1) r += 2;
                if (e[r]      < v1) r += 1;
            }
            float* qs1 = (float*)(sm + FB_QS1);
            float* qs2 = (float*)(sm + FB_QS2);
            int*   rox = (int*)(sm + FB_RO);
            qs1[hl * 64 + srow] = v1;
            qs2[hl * 64 + srow] = v2;
            rox[hl * 64 + srow] = r * 16;
        }
        __syncthreads();

        // ---- step2: 8 warps, warp=(head,arr); lanes 0-15 B, lane 16 Q ----
        // 8 independent RMW chains (vs 4 merged): same wavefronts, 2x chain ILP.
        if (s2doB | s2doQ) {
            float* qs1 = (float*)(sm + FB_QS1);
            float* qs2 = (float*)(sm + FB_QS2);
            int*   rox = (int*)(sm + FB_RO);
            const float* qarr = (s2arr ? qs2 : qs1) + s2hl * 64;
            const int* rop = rox + s2hl * 64;
            const float* ox = outs + s2hl * 16 + s2c;
            float* bk = (float*)(sm + FB_BKT) + (s2hl * 2 + s2arr) * 848 + s2c;
            float* qb = (float*)(sm + FB_QBK) + (s2hl * 2 + s2arr) * 53;
            for (int g = 0; g < 16; g++) {
                int s4 = g * 4;
                int4 r4 = *(const int4*)(rop + s4);       // LDS.128 broadcast
                float4 q4 = *(const float4*)(qarr + s4);  // LDS.128 broadcast
                float x0 = ox[(s4 + 0) * OSTR], x1 = ox[(s4 + 1) * OSTR];
                float x2 = ox[(s4 + 2) * OSTR], x3 = ox[(s4 + 3) * OSTR];
                int r0 = r4.x, r1 = r4.y, r2 = r4.z, r3 = r4.w;
                float v0 = q4.x * x0, v1 = q4.y * x1, v2 = q4.z * x2, v3 = q4.w * x3;
                float w0 = q4.x, w1 = q4.y, w2 = q4.z, w3 = q4.w;
                // dup-merge ladder (group-uniform predicates)
                if (r1 == r0) { v0 += v1; w0 += w1; r1 = TRASH; v1 = 0.f; w1 = 0.f; }
                if (r2 == r0) { v0 += v2; w0 += w2; r2 = TRASH; v2 = 0.f; w2 = 0.f; }
                else if (r2 == r1) { v1 += v2; w1 += w2; r2 = TRASH; v2 = 0.f; w2 = 0.f; }
                if (r3 == r0) { v0 += v3; w0 += w3; r3 = TRASH; v3 = 0.f; w3 = 0.f; }
                else if (r3 == r1) { v1 += v3; w1 += w3; r3 = TRASH; v3 = 0.f; w3 = 0.f; }
                else if (r3 == r2) { v2 += v3; w2 += w3; r3 = TRASH; v3 = 0.f; w3 = 0.f; }
                if (s2doB) {
                    float b0 = bk[r0], b1 = bk[r1], b2 = bk[r2], b3 = bk[r3];
                    bk[r0] = b0 + v0; bk[r1] = b1 + v1; bk[r2] = b2 + v2; bk[r3] = b3 + v3;
                } else {
                    float c0 = qb[r0 >> 4], c1 = qb[r1 >> 4];
                    float c2 = qb[r2 >> 4], c3 = qb[r3 >> 4];
                    qb[r0 >> 4] = c0 + w0; qb[r1 >> 4] = c1 + w1;
                    qb[r2 >> 4] = c2 + w2; qb[r3 >> 4] = c3 + w3;
                }
            }
        }
    }
    __syncthreads();

    // ---- write bucket sums to global ----
    const float* bks = (const float*)(sm + FB_BKT);
    for (int i = tid; i < 4 * 2 * NB * 16; i += 256) {
        int c = i & 15;
        int hr = i >> 4;                    // hl*102 + arr*51 + r
        int hl = hr / 102, rem = hr % 102;
        int arr = rem / NB, r = rem % NB;
        g_bkt[((size_t)((b * H_ + h0 + hl) * 2 + arr) * NB + r) * 16 + c] =
            bks[(hl * 2 + arr) * 848 + r * 16 + c];
    }
    const float* qbs = (const float*)(sm + FB_QBK);
    for (int i = tid; i < 4 * 2 * NB; i += 256) {
        int hl = i / (2 * NB), rem = i % (2 * NB);
        int arr = rem / NB, r = rem % NB;
        g_qbk[((b * H_ + h0 + hl) * 2 + arr) * NB + r] = qbs[(hl * 2 + arr) * 53 + r];
    }
}

// ---------------- finish: scans + Z + output --------------------------------
__global__ __launch_bounds__(64) void finish_kernel(float* __restrict__ out,
                                                    const float* __restrict__ bias) {
    __shared__ float BS[2 * NB * 16];
    __shared__ float QS[2 * NB];
    __shared__ float e1s[T_], e2s[T_], Zs[T_];
    __shared__ int per[T_];
    int h = blockIdx.x, b = blockIdx.y, tid = threadIdx.x;

    const float* gb = g_bkt + (size_t)(b * H_ + h) * 2 * NB * 16;
    for (int i = tid; i < 2 * NB * 16; i += 64) BS[i] = gb[i];
    const float* gq = g_qbk + (b * H_ + h) * 2 * NB;
    for (int i = tid; i < 2 * NB; i += 64) QS[i] = gq[i];
    if (tid < T_) {
        int o = (b * H_ + h) * T_ + tid;
        e1s[tid] = g_e1[o];
        e2s[tid] = g_e2[o];
        per[tid] = g_perm[o];
    }
    __syncthreads();

    if (tid < 32) {
        int arr = tid >> 4, c = tid & 15;
        float run = 0.f;
        if (arr == 0) {
            for (int r = NB - 1; r >= 0; r--) { run += BS[r * 16 + c]; BS[r * 16 + c] = run; }
        } else {
            for (int r = 0; r < NB; r++) { run += BS[(NB + r) * 16 + c]; BS[(NB + r) * 16 + c] = run; }
        }
    } else if (tid < 34) {
        int arr = tid - 32;
        float run = 0.f;
        if (arr == 0) {
            for (int r = NB - 1; r >= 0; r--) { run += QS[r]; QS[r] = run; }
        } else {
            for (int r = 0; r < NB; r++) { run += QS[NB + r]; QS[NB + r] = run; }
        }
    }
    __syncthreads();

    if (tid < T_)
        Zs[tid] = 1.0f / (e1s[tid] * QS[tid + 1] + e2s[tid] * QS[NB + tid]);
    __syncthreads();

    for (int i = tid; i < T_ * 16; i += 64) {
        int si = i >> 4, c = i & 15;
        int t = per[si];
        float o = Zs[si] * (e1s[si] * BS[(si + 1) * 16 + c] + e2s[si] * BS[(NB + si) * 16 + c]);
        out[((size_t)(b * A_) * T_ + t) * HC_ + h * C_ + c] = o + bias[h * C_ + c];
    }
}

// ---------------------------------------------------------------------------
extern "C" void kernel_launch(void* const* d_in, const int* in_sizes, int n_in,
                              void* d_out, int out_size) {
    const float* hin     = (const float*)d_in[0];
    const float* W       = (const float*)d_in[1];
    const float* att_src = (const float*)d_in[2];
    const float* att_dst = (const float*)d_in[3];
    const float* bias    = (const float*)d_in[4];
    float* out = (float*)d_out;

    cudaFuncSetAttribute(fused_kernel, cudaFuncAttributeMaxDynamicSharedMemorySize, SMEM_FUSED);

    prep_kernel<<<(HID_ * HC_ + 255) / 256, 256>>>(W, att_dst);

    xprep_kernel<<<4096, 256>>>(hin);

    dim3 gs(H_, B_);
    adst_sort_kernel<<<gs, 64>>>(hin);

    dim3 gf(8, B_);
    fused_kernel<<<gf, 256, SMEM_FUSED>>>(out, bias, att_src);

    finish_kernel<<<gs, 64>>>(out, bias);
}

// round 15
// speedup vs baseline: 1.5865x; 1.1872x over previous
#include <cuda_runtime.h>
#include <cuda_bf16.h>
#include <cstdint>

#define A_   50
#define T_   50
#define HID_ 128
#define H_   32
#define C_   16
#define B_   32
#define S_   2450          // T_*(A_-1)
#define SP_  2496          // S_ padded to 64
#define HC_  512           // H_*C_
#define NEG_SLOPE 0.2f
#define NB   51            // buckets 0..50
#define OUT4 10240000      // total float4 in output

// ---------------- scratch (device globals; no allocations allowed) --------
__device__ __align__(16) __nv_bfloat16 g_Whi[HC_ * HID_];   // [n][k]
__device__ __align__(16) __nv_bfloat16 g_Wlo[HC_ * HID_];   // [n][k]
__device__ __align__(16) __nv_bfloat16 g_Xhi[(size_t)B_ * SP_ * HID_];  // 20.4 MB
__device__ __align__(16) __nv_bfloat16 g_Xlo[(size_t)B_ * SP_ * HID_];
__device__ float g_eth[B_ * H_ * 64];                       // sorted thresholds (+INF pad)
__device__ float g_e1[B_ * H_ * T_];
__device__ float g_e2[B_ * H_ * T_];
__device__ int   g_perm[B_ * H_ * T_];
__device__ __align__(16) float g_bkt[(size_t)B_ * H_ * 2 * NB * 16];  // 6.7 MB
__device__ float g_qbk[B_ * H_ * 2 * NB];

__device__ __forceinline__ uint32_t smem_u32(const void* p) {
    uint32_t a;
    asm("{ .reg .u64 t; cvta.to.shared.u64 t, %1; cvt.u32.u64 %0, t; }" : "=r"(a) : "l"(p));
    return a;
}

// mma.sync m16n8k16 row.col f32.bf16.bf16.f32
__device__ __forceinline__ void mma_bf16(float* c, const uint32_t* a, const uint32_t* b) {
    asm volatile(
        "mma.sync.aligned.m16n8k16.row.col.f32.bf16.bf16.f32 "
        "{%0,%1,%2,%3}, {%4,%5,%6,%7}, {%8,%9}, {%0,%1,%2,%3};"
        : "+f"(c[0]), "+f"(c[1]), "+f"(c[2]), "+f"(c[3])
        : "r"(a[0]), "r"(a[1]), "r"(a[2]), "r"(a[3]), "r"(b[0]), "r"(b[1]));
}

#define LDMX4(r0, r1, r2, r3, addr) \
    asm volatile("ldmatrix.sync.aligned.m8n8.x4.shared.b16 {%0,%1,%2,%3}, [%4];" \
        : "=r"(r0), "=r"(r1), "=r"(r2), "=r"(r3) : "r"(addr))

#define CP_ASYNC16(dst, src) \
    asm volatile("cp.async.ca.shared.global [%0], [%1], 16;" :: "r"(dst), "l"(src))
#define CP_COMMIT() asm volatile("cp.async.commit_group;")
#define CP_WAIT0()  asm volatile("cp.async.wait_group 0;" ::: "memory")

// ---- fused kernel smem layout (bytes); M=64 rows, 4 heads (N=64) ----
#define ASTR   136
#define OSTR   68
#define NT     39                      // SP_/64
#define FB_WHI  0                      // 17408
#define FB_WLO  17408                  // 17408
#define FB_AHI  34816                  // 17408
#define FB_ALO  52224                  // 17408
#define FB_OUTS FB_AHI                 // outs aliases A_hi ONLY (A_lo stays live)
#define FB_BKT  69632                  // 4h*2arr*53*16*4 = 27136
#define FB_QBK  96768                  // 4*2*53*4 = 1696
#define FB_ETH  98464                  // 4*64*4 = 1024
#define FB_ASC  99488                  // 4*16*4 = 256
#define FB_QS1  99744                  // 4*64*4
#define FB_QS2  100768
#define FB_RO   101792
#define SMEM_FUSED 102816
#define TRASH  816                     // row 51 within a (hl,arr) region (53 rows)

// ---------------- combo: xprep + W-split + adst_sort in ONE launch ---------
// blocks [0,2048): X split; [2048,3072): per-(b,h) adst+sort; [3072,3136): W split
__global__ __launch_bounds__(256) void combo_kernel(const float* __restrict__ hin,
                                                    const float* __restrict__ W,
                                                    const float* __restrict__ att_dst) {
    int bid = blockIdx.x, tid = threadIdx.x;

    if (bid < 2048) {
        // ---- xprep: split X rows (non-ego, s-indexed) to bf16 hi/lo ----
        int idx = bid * 256 + tid;
        const int total = B_ * SP_ * (HID_ / 4);
        for (; idx < total; idx += 2048 * 256) {
            int k4 = idx & 31;
            int rest = idx >> 5;
            int s = rest % SP_;
            int b = rest / SP_;
            float4 v = make_float4(0.f, 0.f, 0.f, 0.f);
            if (s < S_) {
                int a = s % 49 + 1, t = s / 49;
                v = *(const float4*)&hin[(((b * A_ + a) * T_ + t) * HID_) + k4 * 4];
            }
            __nv_bfloat16 hx = __float2bfloat16(v.x), hy = __float2bfloat16(v.y);
            __nv_bfloat16 hz = __float2bfloat16(v.z), hw = __float2bfloat16(v.w);
            __nv_bfloat162 h01; h01.x = hx; h01.y = hy;
            __nv_bfloat162 h23; h23.x = hz; h23.y = hw;
            __nv_bfloat162 l01 = __floats2bfloat162_rn(v.x - __bfloat162float(hx),
                                                       v.y - __bfloat162float(hy));
            __nv_bfloat162 l23 = __floats2bfloat162_rn(v.z - __bfloat162float(hz),
                                                       v.w - __bfloat162float(hw));
            size_t off = ((size_t)(b * SP_ + s)) * HID_ + k4 * 4;
            *(uint2*)&g_Xhi[off] = make_uint2(*(uint32_t*)&h01, *(uint32_t*)&h23);
            *(uint2*)&g_Xlo[off] = make_uint2(*(uint32_t*)&l01, *(uint32_t*)&l23);
        }
    } else if (bid < 3072) {
        // ---- adst + sort per (b,h); v_dst computed locally ----
        __shared__ float hs[T_ * 129];
        __shared__ float vd[HID_];
        __shared__ float dv[64];
        __shared__ float eth[64];
        __shared__ int per[64];
        int sb = bid - 2048;
        int h = sb & 31, b = sb >> 5;

        for (int i = tid; i < T_ * HID_; i += 256) {
            int t = i >> 7, d = i & 127;
            hs[t * 129 + d] = hin[(size_t)(b * A_) * T_ * HID_ + i];   // ego rows contiguous
        }
        if (tid < HID_) {
            float s2 = 0.f;
            #pragma unroll
            for (int c = 0; c < C_; c++)
                s2 += W[(h * C_ + c) * HID_ + tid] * att_dst[h * C_ + c];
            vd[tid] = s2;
        }
        __syncthreads();

        if (tid < 64) {
            float dd = 0.f, key = __int_as_float(0x7f800000);
            if (tid < T_) {
                const float* hr = &hs[tid * 129];
                float a = 0.f;
                #pragma unroll 16
                for (int d = 0; d < HID_; d++) a += hr[d] * vd[d];
                dd = a;
                key = __expf(-a);
            }
            dv[tid] = dd; eth[tid] = key; per[tid] = tid;
        }

        for (int k = 2; k <= 64; k <<= 1) {
            for (int j = k >> 1; j > 0; j >>= 1) {
                __syncthreads();
                if (tid < 64) {
                    int ixj = tid ^ j;
                    if (ixj > tid) {
                        float a = eth[tid], c2 = eth[ixj];
                        bool up = ((tid & k) == 0);
                        if (up ? (a > c2) : (a < c2)) {
                            eth[tid] = c2; eth[ixj] = a;
                            int p = per[tid]; per[tid] = per[ixj]; per[ixj] = p;
                        }
                    }
                }
            }
        }
        __syncthreads();

        if (tid < 64) g_eth[(b * H_ + h) * 64 + tid] = eth[tid];
        if (tid < T_) {
            float d2 = dv[per[tid]];
            int o = (b * H_ + h) * T_ + tid;
            g_e1[o] = __expf(d2);
            g_e2[o] = __expf(NEG_SLOPE * d2);
            g_perm[o] = per[tid];
        }
    } else {
        // ---- W split to bf16 hi/lo ----
        int idx = (bid - 3072) * 256 + tid;     // 16384 threads, 4 els each
        for (; idx < HID_ * HC_; idx += 64 * 256) {
            float w = W[idx];
            __nv_bfloat16 hi = __float2bfloat16(w);
            g_Whi[idx] = hi;
            g_Wlo[idx] = __float2bfloat16(w - __bfloat162float(hi));
        }
    }
}

// ---------------- fused GEMM + bucket accumulation + output fill -----------
// grid (8 head-blocks, 32 b); CTA owns 4 heads (N=64), M=64 rows, 39 tiles.
__global__ __launch_bounds__(256, 2) void fused_kernel(float* __restrict__ gout,
                                                       const float* __restrict__ bias,
                                                       const float* __restrict__ att_src) {
    extern __shared__ char sm[];
    uint32_t sbase = smem_u32(sm);
    int tid = threadIdx.x, wid = tid >> 5, lane = tid & 31;
    int nb = blockIdx.x, b = blockIdx.y;
    int n0 = nb * 64, h0 = nb * 4;
    int rev = (nb + b) & 1;                // decorrelate co-resident CTA phases

    // ---- fill output with broadcast bias (fire-and-forget STG prologue) ----
    {
        int idx4 = (b * 8 + nb) * 256 + tid;          // 0..65535
        float4 bv = ((const float4*)bias)[idx4 & 127];
        float4* o4 = (float4*)gout;
        for (int p = idx4; p < OUT4; p += 65536) o4[p] = bv;
    }

    // ---- resident W (bf16 hi/lo), att_src, thresholds; zero buckets ----
    #pragma unroll
    for (int i = 0; i < 4; i++) {
        int slot = tid + 256 * i;          // 1024 slots = 64 rows x 16 k8
        int row = slot >> 4, k8 = slot & 15;
        size_t off = (size_t)(row * ASTR + k8 * 8) * 2;
        *(uint4*)(sm + FB_WHI + off) = *(const uint4*)&g_Whi[(n0 + row) * HID_ + k8 * 8];
        *(uint4*)(sm + FB_WLO + off) = *(const uint4*)&g_Wlo[(n0 + row) * HID_ + k8 * 8];
    }
    if (tid < 64) ((float*)(sm + FB_ASC))[tid] = att_src[h0 * 16 + tid];
    ((float*)(sm + FB_ETH))[tid] = g_eth[(b * H_ + h0) * 64 + tid];
    for (int i = tid; i < (27136 + 1696) / 4; i += 256)
        ((float*)(sm + FB_BKT))[i] = 0.f;
    __syncthreads();                       // ASC/ETH visible for reg preload

    int wm = wid & 3, wn = wid >> 2;       // m block 16 rows, n block 32 cols
    int at = lane >> 2, kq = (lane & 3) * 2;

    // ---- preload att_src values this thread needs (step1-from-regs) ----
    float ascv[4][2];
    #pragma unroll
    for (int nt = 0; nt < 4; nt++) {
        ascv[nt][0] = ((const float*)(sm + FB_ASC))[wn * 32 + nt * 8 + kq];
        ascv[nt][1] = ((const float*)(sm + FB_ASC))[wn * 32 + nt * 8 + kq + 1];
    }

    // ---- ldmatrix lane addresses (constant across tiles; +32B per ks) ----
    int g8 = lane >> 3, l8 = lane & 7;
    uint32_t aAddrHi = sbase + FB_AHI +
        ((uint32_t)((wm * 16 + (g8 & 1) * 8 + l8) * ASTR + (g8 >> 1) * 8)) * 2;
    uint32_t aAddrLo = aAddrHi + (FB_ALO - FB_AHI);
    uint32_t bAddrHi0 = sbase + FB_WHI +
        ((uint32_t)((wn * 32 + (g8 >> 1) * 8 + l8) * ASTR + (g8 & 1) * 8)) * 2;
    uint32_t bAddrHi1 = bAddrHi0 + 16 * ASTR * 2;
    uint32_t bAddrLo0 = bAddrHi0 + (FB_WLO - FB_WHI);
    uint32_t bAddrLo1 = bAddrHi1 + (FB_WLO - FB_WHI);

    // ---- step2 constants: warps 0-3; lanes 0-15 arr0, 16-31 arr1 ----
    int s2hl = wid;                        // head (warps 0-3 only)
    int s2arr = lane >> 4, s2c = lane & 15;
    bool s2doQ = (s2c == 0);

    const __nv_bfloat16* xhiBase = g_Xhi + (size_t)b * SP_ * HID_;
    const __nv_bfloat16* xloBase = g_Xlo + (size_t)b * SP_ * HID_;

    // per-thread copy slots: 4 rows of A (row = (tid+256i)>>4, k8 = &15)
    int cpRow = tid >> 4, cpK8 = tid & 15;
    uint32_t cpDstHi = sbase + FB_AHI + (uint32_t)(cpRow * ASTR + cpK8 * 8) * 2;
    uint32_t cpDstLo = cpDstHi + (FB_ALO - FB_AHI);

    // ---- prefetch A_lo for first tile ----
    {
        int tl0 = rev ? (NT - 1) : 0;
        #pragma unroll
        for (int i = 0; i < 4; i++) {
            int row = cpRow + i * 16;
            CP_ASYNC16(cpDstLo + (uint32_t)(i * 16 * ASTR * 2),
                       (const char*)(xloBase + (size_t)(tl0 * 64 + row) * HID_ + cpK8 * 8));
        }
        CP_COMMIT();
    }

    for (int tile = 0; tile < NT; tile++) {
        int tl = rev ? (NT - 1 - tile) : tile;
        int s0 = tl * 64;
        __syncthreads();   // step2(t-1) done with outs (A_hi region)

        // ---- copy A_hi(tile) via cp.async; wait for it + earlier lo ----
        #pragma unroll
        for (int i = 0; i < 4; i++) {
            int row = cpRow + i * 16;
            CP_ASYNC16(cpDstHi + (uint32_t)(i * 16 * ASTR * 2),
                       (const char*)(xhiBase + (size_t)(s0 + row) * HID_ + cpK8 * 8));
        }
        CP_COMMIT();
        CP_WAIT0();
        __syncthreads();

        // ---- MMA mainloop: warp tile 16(m) x 32(n), ldmatrix frags ----
        float accA[4][4], accB[4][4];      // hi*hi ; hi*lo + lo*hi
        #pragma unroll
        for (int nt = 0; nt < 4; nt++)
            #pragma unroll
            for (int j = 0; j < 4; j++) { accA[nt][j] = 0.f; accB[nt][j] = 0.f; }

        #pragma unroll
        for (int ks = 0; ks < 8; ks++) {
            uint32_t ko = ks * 32;         // 16 bf16 = 32 bytes per k-step
            uint32_t ah[4], al[4], bh[4][2], bl[4][2];
            LDMX4(ah[0], ah[1], ah[2], ah[3], aAddrHi + ko);
            LDMX4(al[0], al[1], al[2], al[3], aAddrLo + ko);
            LDMX4(bh[0][0], bh[0][1], bh[1][0], bh[1][1], bAddrHi0 + ko);
            LDMX4(bh[2][0], bh[2][1], bh[3][0], bh[3][1], bAddrHi1 + ko);
            LDMX4(bl[0][0], bl[0][1], bl[1][0], bl[1][1], bAddrLo0 + ko);
            LDMX4(bl[2][0], bl[2][1], bl[3][0], bl[3][1], bAddrLo1 + ko);
            #pragma unroll
            for (int nt = 0; nt < 4; nt++) {
                mma_bf16(accA[nt], ah, bh[nt]);
                mma_bf16(accB[nt], ah, bl[nt]);
                mma_bf16(accB[nt], al, bh[nt]);
            }
        }
        __syncthreads();    // done reading A_hi/A_lo

        // ---- prefetch next tile's A_lo (A_lo free now; overlaps step1/2) ----
        {
            int tlN = rev ? (tl - 1) : (tl + 1);
            if (tlN >= 0 && tlN < NT) {
                #pragma unroll
                for (int i = 0; i < 4; i++) {
                    int row = cpRow + i * 16;
                    CP_ASYNC16(cpDstLo + (uint32_t)(i * 16 * ASTR * 2),
                               (const char*)(xloBase + (size_t)(tlN * 64 + row) * HID_ + cpK8 * 8));
                }
                CP_COMMIT();
            }
        }

        // ---- stage D (summed) + step1 from registers ----
        float* outs = (float*)(sm + FB_OUTS);
        float sum0[4], sum1[4], sum2[4], sum3[4];
        {
            int r = wm * 16 + at;
            #pragma unroll
            for (int nt = 0; nt < 4; nt++) {
                sum0[nt] = accA[nt][0] + accB[nt][0];
                sum1[nt] = accA[nt][1] + accB[nt][1];
                sum2[nt] = accA[nt][2] + accB[nt][2];
                sum3[nt] = accA[nt][3] + accB[nt][3];
                int cc = wn * 32 + nt * 8 + kq;
                *(float2*)&outs[r * OSTR + cc]       = make_float2(sum0[nt], sum1[nt]);
                *(float2*)&outs[(r + 8) * OSTR + cc] = make_float2(sum2[nt], sum3[nt]);
            }
        }
        {
            // partial a_src dots from registers
            float dA = sum0[0] * ascv[0][0] + sum1[0] * ascv[0][1]
                     + sum0[1] * ascv[1][0] + sum1[1] * ascv[1][1];   // (r, h0)
            float dB = sum0[2] * ascv[2][0] + sum1[2] * ascv[2][1]
                     + sum0[3] * ascv[3][0] + sum1[3] * ascv[3][1];   // (r, h1)
            float dC = sum2[0] * ascv[0][0] + sum3[0] * ascv[0][1]
                     + sum2[1] * ascv[1][0] + sum3[1] * ascv[1][1];   // (r+8, h0)
            float dD = sum2[2] * ascv[2][0] + sum3[2] * ascv[2][1]
                     + sum2[3] * ascv[3][0] + sum3[3] * ascv[3][1];   // (r+8, h1)
            dA += __shfl_xor_sync(0xffffffffu, dA, 1);
            dA += __shfl_xor_sync(0xffffffffu, dA, 2);
            dB += __shfl_xor_sync(0xffffffffu, dB, 1);
            dB += __shfl_xor_sync(0xffffffffu, dB, 2);
            dC += __shfl_xor_sync(0xffffffffu, dC, 1);
            dC += __shfl_xor_sync(0xffffffffu, dC, 2);
            dD += __shfl_xor_sync(0xffffffffu, dD, 1);
            dD += __shfl_xor_sync(0xffffffffu, dD, 2);
            int sel = lane & 3;
            float dot = (sel == 0) ? dA : (sel == 1) ? dB : (sel == 2) ? dC : dD;
            int srow = wm * 16 + at + (sel >> 1) * 8;
            int hl = 2 * wn + (sel & 1);
            float v1 = 0.f, v2 = 0.f;
            int r = 0;
            if (s0 + srow < S_) {
                v1 = __expf(dot);
                v2 = __expf(NEG_SLOPE * dot);
                const float* e = (const float*)(sm + FB_ETH) + hl * 64;
                if (e[r + 31] < v1) r += 32;
                if (e[r + 15] < v1) r += 16;
                if (e[r + 7]  < v1) r += 8;
                if (e[r + 3]  < v1) r += 4;
                if (e[r + 1]  < v1) r += 2;
                if (e[r]      < v1) r += 1;
            }
            float* qs1 = (float*)(sm + FB_QS1);
            float* qs2 = (float*)(sm + FB_QS2);
            int*   rox = (int*)(sm + FB_RO);
            qs1[hl * 64 + srow] = v1;
            qs2[hl * 64 + srow] = v2;
            rox[hl * 64 + srow] = r * 16;
        }
        __syncthreads();

        // ---- step2 merged: warps 0-3; lanes 0-15 arr0(q1), 16-31 arr1(q2) ----
        if (wid < 4) {
            float* qs1 = (float*)(sm + FB_QS1);
            float* qs2 = (float*)(sm + FB_QS2);
            int*   rox = (int*)(sm + FB_RO);
            const float* qarr = (s2arr ? qs2 : qs1) + s2hl * 64;
            const int* rop = rox + s2hl * 64;
            const float* ox = outs + s2hl * 16 + s2c;
            float* bk = (float*)(sm + FB_BKT) + (s2hl * 2 + s2arr) * 848 + s2c;
            float* qb = (float*)(sm + FB_QBK) + (s2hl * 2 + s2arr) * 53;
            for (int g = 0; g < 16; g++) {
                int s4 = g * 4;
                int4 r4 = *(const int4*)(rop + s4);
                float4 q4 = *(const float4*)(qarr + s4);
                float x0 = ox[(s4 + 0) * OSTR], x1 = ox[(s4 + 1) * OSTR];
                float x2 = ox[(s4 + 2) * OSTR], x3 = ox[(s4 + 3) * OSTR];
                int r0 = r4.x, r1 = r4.y, r2 = r4.z, r3 = r4.w;
                float v0 = q4.x * x0, v1 = q4.y * x1, v2 = q4.z * x2, v3 = q4.w * x3;
                float w0 = q4.x, w1 = q4.y, w2 = q4.z, w3 = q4.w;
                if (r1 == r0) { v0 += v1; w0 += w1; r1 = TRASH; v1 = 0.f; w1 = 0.f; }
                if (r2 == r0) { v0 += v2; w0 += w2; r2 = TRASH; v2 = 0.f; w2 = 0.f; }
                else if (r2 == r1) { v1 += v2; w1 += w2; r2 = TRASH; v2 = 0.f; w2 = 0.f; }
                if (r3 == r0) { v0 += v3; w0 += w3; r3 = TRASH; v3 = 0.f; w3 = 0.f; }
                else if (r3 == r1) { v1 += v3; w1 += w3; r3 = TRASH; v3 = 0.f; w3 = 0.f; }
                else if (r3 == r2) { v2 += v3; w2 += w3; r3 = TRASH; v3 = 0.f; w3 = 0.f; }
                float b0 = bk[r0], b1 = bk[r1], b2 = bk[r2], b3 = bk[r3];
                bk[r0] = b0 + v0; bk[r1] = b1 + v1; bk[r2] = b2 + v2; bk[r3] = b3 + v3;
                if (s2doQ) {
                    float c0 = qb[r0 >> 4], c1 = qb[r1 >> 4];
                    float c2 = qb[r2 >> 4], c3 = qb[r3 >> 4];
                    qb[r0 >> 4] = c0 + w0; qb[r1 >> 4] = c1 + w1;
                    qb[r2 >> 4] = c2 + w2; qb[r3 >> 4] = c3 + w3;
                }
            }
        }
    }
    __syncthreads();

    // ---- write bucket sums to global ----
    const float* bks = (const float*)(sm + FB_BKT);
    for (int i = tid; i < 4 * 2 * NB * 16; i += 256) {
        int c = i & 15;
        int hr = i >> 4;                    // hl*102 + arr*51 + r
        int hl = hr / 102, rem = hr % 102;
        int arr = rem / NB, r = rem % NB;
        g_bkt[((size_t)((b * H_ + h0 + hl) * 2 + arr) * NB + r) * 16 + c] =
            bks[(hl * 2 + arr) * 848 + r * 16 + c];
    }
    const float* qbs = (const float*)(sm + FB_QBK);
    for (int i = tid; i < 4 * 2 * NB; i += 256) {
        int hl = i / (2 * NB), rem = i % (2 * NB);
        int arr = rem / NB, r = rem % NB;
        g_qbk[((b * H_ + h0 + hl) * 2 + arr) * NB + r] = qbs[(hl * 2 + arr) * 53 + r];
    }
}

// ---------------- finish: scans + Z + output --------------------------------
__global__ __launch_bounds__(64) void finish_kernel(float* __restrict__ out,
                                                    const float* __restrict__ bias) {
    __shared__ float BS[2 * NB * 16];
    __shared__ float QS[2 * NB];
    __shared__ float e1s[T_], e2s[T_], Zs[T_];
    __shared__ int per[T_];
    int h = blockIdx.x, b = blockIdx.y, tid = threadIdx.x;

    const float* gb = g_bkt + (size_t)(b * H_ + h) * 2 * NB * 16;
    for (int i = tid; i < 2 * NB * 16; i += 64) BS[i] = gb[i];
    const float* gq = g_qbk + (b * H_ + h) * 2 * NB;
    for (int i = tid; i < 2 * NB; i += 64) QS[i] = gq[i];
    if (tid < T_) {
        int o = (b * H_ + h) * T_ + tid;
        e1s[tid] = g_e1[o];
        e2s[tid] = g_e2[o];
        per[tid] = g_perm[o];
    }
    __syncthreads();

    if (tid < 32) {
        int arr = tid >> 4, c = tid & 15;
        float run = 0.f;
        if (arr == 0) {
            for (int r = NB - 1; r >= 0; r--) { run += BS[r * 16 + c]; BS[r * 16 + c] = run; }
        } else {
            for (int r = 0; r < NB; r++) { run += BS[(NB + r) * 16 + c]; BS[(NB + r) * 16 + c] = run; }
        }
    } else if (tid < 34) {
        int arr = tid - 32;
        float run = 0.f;
        if (arr == 0) {
            for (int r = NB - 1; r >= 0; r--) { run += QS[r]; QS[r] = run; }
        } else {
            for (int r = 0; r < NB; r++) { run += QS[NB + r]; QS[NB + r] = run; }
        }
    }
    __syncthreads();

    if (tid < T_)
        Zs[tid] = 1.0f / (e1s[tid] * QS[tid + 1] + e2s[tid] * QS[NB + tid]);
    __syncthreads();

    for (int i = tid; i < T_ * 16; i += 64) {
        int si = i >> 4, c = i & 15;
        int t = per[si];
        float o = Zs[si] * (e1s[si] * BS[(si + 1) * 16 + c] + e2s[si] * BS[(NB + si) * 16 + c]);
        out[((size_t)(b * A_) * T_ + t) * HC_ + h * C_ + c] = o + bias[h * C_ + c];
    }
}

// ---------------------------------------------------------------------------
extern "C" void kernel_launch(void* const* d_in, const int* in_sizes, int n_in,
                              void* d_out, int out_size) {
    const float* hin     = (const float*)d_in[0];
    const float* W       = (const float*)d_in[1];
    const float* att_src = (const float*)d_in[2];
    const float* att_dst = (const float*)d_in[3];
    const float* bias    = (const float*)d_in[4];
    float* out = (float*)d_out;

    cudaFuncSetAttribute(fused_kernel, cudaFuncAttributeMaxDynamicSharedMemorySize, SMEM_FUSED);

    combo_kernel<<<3136, 256>>>(hin, W, att_dst);

    dim3 gf(8, B_);
    fused_kernel<<<gf, 256, SMEM_FUSED>>>(out, bias, att_src);

    dim3 gs(H_, B_);
    finish_kernel<<<gs, 64>>>(out, bias);
}

// round 16
// speedup vs baseline: 1.7161x; 1.0817x over previous
#include <cuda_runtime.h>
#include <cuda_bf16.h>
#include <cstdint>

#define A_   50
#define T_   50
#define HID_ 128
#define H_   32
#define C_   16
#define B_   32
#define S_   2450          // T_*(A_-1)
#define SP_  2496          // S_ padded to 64
#define HC_  512           // H_*C_
#define NEG_SLOPE 0.2f
#define NB   51            // buckets 0..50
#define OUT4 10240000      // total float4 in output

// ---------------- scratch (device globals; no allocations allowed) --------
__device__ __align__(16) __nv_bfloat16 g_Whi[HC_ * HID_];   // [n][k]
__device__ __align__(16) __nv_bfloat16 g_Wlo[HC_ * HID_];   // [n][k]
__device__ __align__(16) __nv_bfloat16 g_Xhi[(size_t)B_ * SP_ * HID_];  // 20.4 MB
__device__ __align__(16) __nv_bfloat16 g_Xlo[(size_t)B_ * SP_ * HID_];
__device__ float g_eth[B_ * H_ * 64];                       // sorted thresholds (+INF pad)
__device__ float g_e1[B_ * H_ * T_];
__device__ float g_e2[B_ * H_ * T_];
__device__ int   g_perm[B_ * H_ * T_];
__device__ __align__(16) float g_bkt[(size_t)B_ * H_ * 2 * NB * 16];  // 6.7 MB
__device__ float g_qbk[B_ * H_ * 2 * NB];

__device__ __forceinline__ uint32_t smem_u32(const void* p) {
    uint32_t a;
    asm("{ .reg .u64 t; cvta.to.shared.u64 t, %1; cvt.u32.u64 %0, t; }" : "=r"(a) : "l"(p));
    return a;
}

// mma.sync m16n8k16 row.col f32.bf16.bf16.f32
__device__ __forceinline__ void mma_bf16(float* c, const uint32_t* a, const uint32_t* b) {
    asm volatile(
        "mma.sync.aligned.m16n8k16.row.col.f32.bf16.bf16.f32 "
        "{%0,%1,%2,%3}, {%4,%5,%6,%7}, {%8,%9}, {%0,%1,%2,%3};"
        : "+f"(c[0]), "+f"(c[1]), "+f"(c[2]), "+f"(c[3])
        : "r"(a[0]), "r"(a[1]), "r"(a[2]), "r"(a[3]), "r"(b[0]), "r"(b[1]));
}

#define LDMX4(r0, r1, r2, r3, addr) \
    asm volatile("ldmatrix.sync.aligned.m8n8.x4.shared.b16 {%0,%1,%2,%3}, [%4];" \
        : "=r"(r0), "=r"(r1), "=r"(r2), "=r"(r3) : "r"(addr))

#define CP_ASYNC16(dst, src) \
    asm volatile("cp.async.ca.shared.global [%0], [%1], 16;" :: "r"(dst), "l"(src))
#define CP_COMMIT() asm volatile("cp.async.commit_group;")
#define CP_WAIT0()  asm volatile("cp.async.wait_group 0;" ::: "memory")

// ---- fused kernel smem layout (bytes); M=64 rows, 4 heads (N=64) ----
#define ASTR   136
#define OSTR   68
#define NT     39                      // SP_/64
#define FB_WHI  0                      // 17408
#define FB_WLO  17408                  // 17408
#define FB_AHI  34816                  // 17408
#define FB_ALO  52224                  // 17408
#define FB_OUTS FB_AHI                 // outs aliases A_hi ONLY (A_lo stays live)
#define FB_BKT  69632                  // 4h*2arr*53*16*4 = 27136
#define FB_QBK  96768                  // 4*2*53*4 = 1696
#define FB_ETH  98464                  // 4*64*4 = 1024
#define FB_ASC  99488                  // 4*16*4 = 256
#define FB_QS1  99744                  // 4*64*4
#define FB_QS2  100768
#define FB_RO   101792
#define SMEM_FUSED 102816
#define TRASH  816                     // row 51 within a (hl,arr) region (53 rows)

// ---------------- combo: xprep + W-split + adst_sort in ONE launch ---------
// blocks [0,2048): X split; [2048,3072): per-(b,h) adst+sort; [3072,3136): W split
__global__ __launch_bounds__(256) void combo_kernel(const float* __restrict__ hin,
                                                    const float* __restrict__ W,
                                                    const float* __restrict__ att_dst) {
    int bid = blockIdx.x, tid = threadIdx.x;

    if (bid < 2048) {
        // ---- xprep: split X rows (non-ego, s-indexed) to bf16 hi/lo ----
        int idx = bid * 256 + tid;
        const int total = B_ * SP_ * (HID_ / 4);
        for (; idx < total; idx += 2048 * 256) {
            int k4 = idx & 31;
            int rest = idx >> 5;
            int s = rest % SP_;
            int b = rest / SP_;
            float4 v = make_float4(0.f, 0.f, 0.f, 0.f);
            if (s < S_) {
                int a = s % 49 + 1, t = s / 49;
                v = *(const float4*)&hin[(((b * A_ + a) * T_ + t) * HID_) + k4 * 4];
            }
            __nv_bfloat16 hx = __float2bfloat16(v.x), hy = __float2bfloat16(v.y);
            __nv_bfloat16 hz = __float2bfloat16(v.z), hw = __float2bfloat16(v.w);
            __nv_bfloat162 h01; h01.x = hx; h01.y = hy;
            __nv_bfloat162 h23; h23.x = hz; h23.y = hw;
            __nv_bfloat162 l01 = __floats2bfloat162_rn(v.x - __bfloat162float(hx),
                                                       v.y - __bfloat162float(hy));
            __nv_bfloat162 l23 = __floats2bfloat162_rn(v.z - __bfloat162float(hz),
                                                       v.w - __bfloat162float(hw));
            size_t off = ((size_t)(b * SP_ + s)) * HID_ + k4 * 4;
            *(uint2*)&g_Xhi[off] = make_uint2(*(uint32_t*)&h01, *(uint32_t*)&h23);
            *(uint2*)&g_Xlo[off] = make_uint2(*(uint32_t*)&l01, *(uint32_t*)&l23);
        }
    } else if (bid < 3072) {
        // ---- adst + sort per (b,h); v_dst computed locally ----
        __shared__ float hs[T_ * 129];
        __shared__ float vd[HID_];
        __shared__ float dv[64];
        __shared__ float eth[64];
        __shared__ int per[64];
        int sb = bid - 2048;
        int h = sb & 31, b = sb >> 5;

        for (int i = tid; i < T_ * HID_; i += 256) {
            int t = i >> 7, d = i & 127;
            hs[t * 129 + d] = hin[(size_t)(b * A_) * T_ * HID_ + i];   // ego rows contiguous
        }
        if (tid < HID_) {
            float s2 = 0.f;
            #pragma unroll
            for (int c = 0; c < C_; c++)
                s2 += W[(h * C_ + c) * HID_ + tid] * att_dst[h * C_ + c];
            vd[tid] = s2;
        }
        __syncthreads();

        if (tid < 64) {
            float dd = 0.f, key = __int_as_float(0x7f800000);
            if (tid < T_) {
                const float* hr = &hs[tid * 129];
                float a = 0.f;
                #pragma unroll 16
                for (int d = 0; d < HID_; d++) a += hr[d] * vd[d];
                dd = a;
                key = __expf(-a);
            }
            dv[tid] = dd; eth[tid] = key; per[tid] = tid;
        }

        for (int k = 2; k <= 64; k <<= 1) {
            for (int j = k >> 1; j > 0; j >>= 1) {
                __syncthreads();
                if (tid < 64) {
                    int ixj = tid ^ j;
                    if (ixj > tid) {
                        float a = eth[tid], c2 = eth[ixj];
                        bool up = ((tid & k) == 0);
                        if (up ? (a > c2) : (a < c2)) {
                            eth[tid] = c2; eth[ixj] = a;
                            int p = per[tid]; per[tid] = per[ixj]; per[ixj] = p;
                        }
                    }
                }
            }
        }
        __syncthreads();

        if (tid < 64) g_eth[(b * H_ + h) * 64 + tid] = eth[tid];
        if (tid < T_) {
            float d2 = dv[per[tid]];
            int o = (b * H_ + h) * T_ + tid;
            g_e1[o] = __expf(d2);
            g_e2[o] = __expf(NEG_SLOPE * d2);
            g_perm[o] = per[tid];
        }
    } else {
        // ---- W split to bf16 hi/lo ----
        int idx = (bid - 3072) * 256 + tid;     // 16384 threads, 4 els each
        for (; idx < HID_ * HC_; idx += 64 * 256) {
            float w = W[idx];
            __nv_bfloat16 hi = __float2bfloat16(w);
            g_Whi[idx] = hi;
            g_Wlo[idx] = __float2bfloat16(w - __bfloat162float(hi));
        }
    }
}

// ---------------- fused GEMM + bucket accumulation + output fill -----------
// grid (8 head-blocks, 32 b); CTA owns 4 heads (N=64), M=64 rows, 39 tiles.
__global__ __launch_bounds__(256, 2) void fused_kernel(float* __restrict__ gout,
                                                       const float* __restrict__ bias,
                                                       const float* __restrict__ att_src) {
    extern __shared__ char sm[];
    uint32_t sbase = smem_u32(sm);
    int tid = threadIdx.x, wid = tid >> 5, lane = tid & 31;
    int nb = blockIdx.x, b = blockIdx.y;
    int n0 = nb * 64, h0 = nb * 4;
    int rev = (nb + b) & 1;                // decorrelate co-resident CTA phases

    // ---- fill output with broadcast bias (fire-and-forget STG prologue) ----
    {
        int idx4 = (b * 8 + nb) * 256 + tid;          // 0..65535
        float4 bv = ((const float4*)bias)[idx4 & 127];
        float4* o4 = (float4*)gout;
        for (int p = idx4; p < OUT4; p += 65536) o4[p] = bv;
    }

    // ---- resident W (bf16 hi/lo), att_src, thresholds; zero buckets ----
    #pragma unroll
    for (int i = 0; i < 4; i++) {
        int slot = tid + 256 * i;          // 1024 slots = 64 rows x 16 k8
        int row = slot >> 4, k8 = slot & 15;
        size_t off = (size_t)(row * ASTR + k8 * 8) * 2;
        *(uint4*)(sm + FB_WHI + off) = *(const uint4*)&g_Whi[(n0 + row) * HID_ + k8 * 8];
        *(uint4*)(sm + FB_WLO + off) = *(const uint4*)&g_Wlo[(n0 + row) * HID_ + k8 * 8];
    }
    if (tid < 64) ((float*)(sm + FB_ASC))[tid] = att_src[h0 * 16 + tid];
    ((float*)(sm + FB_ETH))[tid] = g_eth[(b * H_ + h0) * 64 + tid];
    for (int i = tid; i < (27136 + 1696) / 4; i += 256)
        ((float*)(sm + FB_BKT))[i] = 0.f;
    __syncthreads();                       // ASC/ETH visible for reg preload

    int wm = wid & 3, wn = wid >> 2;       // m block 16 rows, n block 32 cols
    int at = lane >> 2, kq = (lane & 3) * 2;

    // ---- preload att_src values this thread needs (step1-from-regs) ----
    float ascv[4][2];
    #pragma unroll
    for (int nt = 0; nt < 4; nt++) {
        ascv[nt][0] = ((const float*)(sm + FB_ASC))[wn * 32 + nt * 8 + kq];
        ascv[nt][1] = ((const float*)(sm + FB_ASC))[wn * 32 + nt * 8 + kq + 1];
    }

    // ---- ldmatrix lane addresses (constant across tiles; +32B per ks) ----
    int g8 = lane >> 3, l8 = lane & 7;
    uint32_t aAddrHi = sbase + FB_AHI +
        ((uint32_t)((wm * 16 + (g8 & 1) * 8 + l8) * ASTR + (g8 >> 1) * 8)) * 2;
    uint32_t aAddrLo = aAddrHi + (FB_ALO - FB_AHI);
    uint32_t bAddrHi0 = sbase + FB_WHI +
        ((uint32_t)((wn * 32 + (g8 >> 1) * 8 + l8) * ASTR + (g8 & 1) * 8)) * 2;
    uint32_t bAddrHi1 = bAddrHi0 + 16 * ASTR * 2;
    uint32_t bAddrLo0 = bAddrHi0 + (FB_WLO - FB_WHI);
    uint32_t bAddrLo1 = bAddrHi1 + (FB_WLO - FB_WHI);

    // ---- step2 constants ----
    // warps 0-3 (B):   warp = head; lanes 0-15 arr0, 16-31 arr1
    // warps 4-7 (Q):   warp = head+4; lane 0 -> arr0, lane 16 -> arr1
    int s2hl = wid & 3;
    int s2arr = lane >> 4, s2c = lane & 15;

    const __nv_bfloat16* xhiBase = g_Xhi + (size_t)b * SP_ * HID_;
    const __nv_bfloat16* xloBase = g_Xlo + (size_t)b * SP_ * HID_;

    // per-thread copy slots: 4 rows of A (row = (tid+256i)>>4, k8 = &15)
    int cpRow = tid >> 4, cpK8 = tid & 15;
    uint32_t cpDstHi = sbase + FB_AHI + (uint32_t)(cpRow * ASTR + cpK8 * 8) * 2;
    uint32_t cpDstLo = cpDstHi + (FB_ALO - FB_AHI);

    // ---- prefetch A_lo for first tile ----
    {
        int tl0 = rev ? (NT - 1) : 0;
        #pragma unroll
        for (int i = 0; i < 4; i++) {
            int row = cpRow + i * 16;
            CP_ASYNC16(cpDstLo + (uint32_t)(i * 16 * ASTR * 2),
                       (const char*)(xloBase + (size_t)(tl0 * 64 + row) * HID_ + cpK8 * 8));
        }
        CP_COMMIT();
    }

    for (int tile = 0; tile < NT; tile++) {
        int tl = rev ? (NT - 1 - tile) : tile;
        int s0 = tl * 64;
        __syncthreads();   // step2(t-1) done with outs (A_hi region)

        // ---- copy A_hi(tile) via cp.async; wait for it + earlier lo ----
        #pragma unroll
        for (int i = 0; i < 4; i++) {
            int row = cpRow + i * 16;
            CP_ASYNC16(cpDstHi + (uint32_t)(i * 16 * ASTR * 2),
                       (const char*)(xhiBase + (size_t)(s0 + row) * HID_ + cpK8 * 8));
        }
        CP_COMMIT();
        CP_WAIT0();
        __syncthreads();

        // ---- MMA mainloop: warp tile 16(m) x 32(n), ldmatrix frags ----
        float accA[4][4], accB[4][4];      // hi*hi ; hi*lo + lo*hi
        #pragma unroll
        for (int nt = 0; nt < 4; nt++)
            #pragma unroll
            for (int j = 0; j < 4; j++) { accA[nt][j] = 0.f; accB[nt][j] = 0.f; }

        #pragma unroll
        for (int ks = 0; ks < 8; ks++) {
            uint32_t ko = ks * 32;         // 16 bf16 = 32 bytes per k-step
            uint32_t ah[4], al[4], bh[4][2], bl[4][2];
            LDMX4(ah[0], ah[1], ah[2], ah[3], aAddrHi + ko);
            LDMX4(al[0], al[1], al[2], al[3], aAddrLo + ko);
            LDMX4(bh[0][0], bh[0][1], bh[1][0], bh[1][1], bAddrHi0 + ko);
            LDMX4(bh[2][0], bh[2][1], bh[3][0], bh[3][1], bAddrHi1 + ko);
            LDMX4(bl[0][0], bl[0][1], bl[1][0], bl[1][1], bAddrLo0 + ko);
            LDMX4(bl[2][0], bl[2][1], bl[3][0], bl[3][1], bAddrLo1 + ko);
            #pragma unroll
            for (int nt = 0; nt < 4; nt++) {
                mma_bf16(accA[nt], ah, bh[nt]);
                mma_bf16(accB[nt], ah, bl[nt]);
                mma_bf16(accB[nt], al, bh[nt]);
            }
        }
        __syncthreads();    // done reading A_hi/A_lo

        // ---- prefetch next tile's A_lo (A_lo free now; overlaps step1/2) ----
        {
            int tlN = rev ? (tl - 1) : (tl + 1);
            if (tlN >= 0 && tlN < NT) {
                #pragma unroll
                for (int i = 0; i < 4; i++) {
                    int row = cpRow + i * 16;
                    CP_ASYNC16(cpDstLo + (uint32_t)(i * 16 * ASTR * 2),
                               (const char*)(xloBase + (size_t)(tlN * 64 + row) * HID_ + cpK8 * 8));
                }
                CP_COMMIT();
            }
        }

        // ---- stage D (summed) + step1 from registers ----
        float* outs = (float*)(sm + FB_OUTS);
        float sum0[4], sum1[4], sum2[4], sum3[4];
        {
            int r = wm * 16 + at;
            #pragma unroll
            for (int nt = 0; nt < 4; nt++) {
                sum0[nt] = accA[nt][0] + accB[nt][0];
                sum1[nt] = accA[nt][1] + accB[nt][1];
                sum2[nt] = accA[nt][2] + accB[nt][2];
                sum3[nt] = accA[nt][3] + accB[nt][3];
                int cc = wn * 32 + nt * 8 + kq;
                *(float2*)&outs[r * OSTR + cc]       = make_float2(sum0[nt], sum1[nt]);
                *(float2*)&outs[(r + 8) * OSTR + cc] = make_float2(sum2[nt], sum3[nt]);
            }
        }
        {
            // partial a_src dots from registers
            float dA = sum0[0] * ascv[0][0] + sum1[0] * ascv[0][1]
                     + sum0[1] * ascv[1][0] + sum1[1] * ascv[1][1];   // (r, h0)
            float dB = sum0[2] * ascv[2][0] + sum1[2] * ascv[2][1]
                     + sum0[3] * ascv[3][0] + sum1[3] * ascv[3][1];   // (r, h1)
            float dC = sum2[0] * ascv[0][0] + sum3[0] * ascv[0][1]
                     + sum2[1] * ascv[1][0] + sum3[1] * ascv[1][1];   // (r+8, h0)
            float dD = sum2[2] * ascv[2][0] + sum3[2] * ascv[2][1]
                     + sum2[3] * ascv[3][0] + sum3[3] * ascv[3][1];   // (r+8, h1)
            dA += __shfl_xor_sync(0xffffffffu, dA, 1);
            dA += __shfl_xor_sync(0xffffffffu, dA, 2);
            dB += __shfl_xor_sync(0xffffffffu, dB, 1);
            dB += __shfl_xor_sync(0xffffffffu, dB, 2);
            dC += __shfl_xor_sync(0xffffffffu, dC, 1);
            dC += __shfl_xor_sync(0xffffffffu, dC, 2);
            dD += __shfl_xor_sync(0xffffffffu, dD, 1);
            dD += __shfl_xor_sync(0xffffffffu, dD, 2);
            int sel = lane & 3;
            float dot = (sel == 0) ? dA : (sel == 1) ? dB : (sel == 2) ? dC : dD;
            int srow = wm * 16 + at + (sel >> 1) * 8;
            int hl = 2 * wn + (sel & 1);
            float v1 = 0.f, v2 = 0.f;
            int r = 0;
            if (s0 + srow < S_) {
                v1 = __expf(dot);
                v2 = __expf(NEG_SLOPE * dot);
                const float* e = (const float*)(sm + FB_ETH) + hl * 64;
                if (e[r + 31] < v1) r += 32;
                if (e[r + 15] < v1) r += 16;
                if (e[r + 7]  < v1) r += 8;
                if (e[r + 3]  < v1) r += 4;
                if (e[r + 1]  < v1) r += 2;
                if (e[r]      < v1) r += 1;
            }
            float* qs1 = (float*)(sm + FB_QS1);
            float* qs2 = (float*)(sm + FB_QS2);
            int*   rox = (int*)(sm + FB_RO);
            qs1[hl * 64 + srow] = v1;
            qs2[hl * 64 + srow] = v2;
            rox[hl * 64 + srow] = r * 16;
        }
        __syncthreads();

        // ---- step2 split: warps 0-3 do B buckets; warps 4-7 do Q scalars ----
        {
            float* qs1 = (float*)(sm + FB_QS1);
            float* qs2 = (float*)(sm + FB_QS2);
            int*   rox = (int*)(sm + FB_RO);
            const float* qarr = (s2arr ? qs2 : qs1) + s2hl * 64;
            const int* rop = rox + s2hl * 64;
            if (wid < 4) {
                // B accumulation, lanes 0-15 arr0, 16-31 arr1 (no Q duty)
                const float* ox = outs + s2hl * 16 + s2c;
                float* bk = (float*)(sm + FB_BKT) + (s2hl * 2 + s2arr) * 848 + s2c;
                for (int g = 0; g < 16; g++) {
                    int s4 = g * 4;
                    int4 r4 = *(const int4*)(rop + s4);
                    float4 q4 = *(const float4*)(qarr + s4);
                    float x0 = ox[(s4 + 0) * OSTR], x1 = ox[(s4 + 1) * OSTR];
                    float x2 = ox[(s4 + 2) * OSTR], x3 = ox[(s4 + 3) * OSTR];
                    int r0 = r4.x, r1 = r4.y, r2 = r4.z, r3 = r4.w;
                    float v0 = q4.x * x0, v1 = q4.y * x1, v2 = q4.z * x2, v3 = q4.w * x3;
                    if (r1 == r0) { v0 += v1; r1 = TRASH; v1 = 0.f; }
                    if (r2 == r0) { v0 += v2; r2 = TRASH; v2 = 0.f; }
                    else if (r2 == r1) { v1 += v2; r2 = TRASH; v2 = 0.f; }
                    if (r3 == r0) { v0 += v3; r3 = TRASH; v3 = 0.f; }
                    else if (r3 == r1) { v1 += v3; r3 = TRASH; v3 = 0.f; }
                    else if (r3 == r2) { v2 += v3; r3 = TRASH; v3 = 0.f; }
                    float b0 = bk[r0], b1 = bk[r1], b2 = bk[r2], b3 = bk[r3];
                    bk[r0] = b0 + v0; bk[r1] = b1 + v1; bk[r2] = b2 + v2; bk[r3] = b3 + v3;
                }
            } else if (s2c == 0) {
                // Q accumulation: warp 4+hl; lane 0 -> arr0, lane 16 -> arr1
                float* qb = (float*)(sm + FB_QBK) + (s2hl * 2 + s2arr) * 53;
                for (int g = 0; g < 16; g++) {
                    int s4 = g * 4;
                    int4 r4 = *(const int4*)(rop + s4);
                    float4 q4 = *(const float4*)(qarr + s4);
                    int r0 = r4.x >> 4, r1 = r4.y >> 4, r2 = r4.z >> 4, r3 = r4.w >> 4;
                    float w0 = q4.x, w1 = q4.y, w2 = q4.z, w3 = q4.w;
                    if (r1 == r0) { w0 += w1; r1 = 51; w1 = 0.f; }
                    if (r2 == r0) { w0 += w2; r2 = 51; w2 = 0.f; }
                    else if (r2 == r1) { w1 += w2; r2 = 51; w2 = 0.f; }
                    if (r3 == r0) { w0 += w3; r3 = 51; w3 = 0.f; }
                    else if (r3 == r1) { w1 += w3; r3 = 51; w3 = 0.f; }
                    else if (r3 == r2) { w2 += w3; r3 = 51; w3 = 0.f; }
                    float c0 = qb[r0], c1 = qb[r1], c2 = qb[r2], c3 = qb[r3];
                    qb[r0] = c0 + w0; qb[r1] = c1 + w1; qb[r2] = c2 + w2; qb[r3] = c3 + w3;
                }
            }
        }
    }
    __syncthreads();

    // ---- write bucket sums to global ----
    const float* bks = (const float*)(sm + FB_BKT);
    for (int i = tid; i < 4 * 2 * NB * 16; i += 256) {
        int c = i & 15;
        int hr = i >> 4;                    // hl*102 + arr*51 + r
        int hl = hr / 102, rem = hr % 102;
        int arr = rem / NB, r = rem % NB;
        g_bkt[((size_t)((b * H_ + h0 + hl) * 2 + arr) * NB + r) * 16 + c] =
            bks[(hl * 2 + arr) * 848 + r * 16 + c];
    }
    const float* qbs = (const float*)(sm + FB_QBK);
    for (int i = tid; i < 4 * 2 * NB; i += 256) {
        int hl = i / (2 * NB), rem = i % (2 * NB);
        int arr = rem / NB, r = rem % NB;
        g_qbk[((b * H_ + h0 + hl) * 2 + arr) * NB + r] = qbs[(hl * 2 + arr) * 53 + r];
    }
}

// ---------------- finish: scans + Z + output --------------------------------
__global__ __launch_bounds__(64) void finish_kernel(float* __restrict__ out,
                                                    const float* __restrict__ bias) {
    __shared__ float BS[2 * NB * 16];
    __shared__ float QS[2 * NB];
    __shared__ float e1s[T_], e2s[T_], Zs[T_];
    __shared__ int per[T_];
    int h = blockIdx.x, b = blockIdx.y, tid = threadIdx.x;

    const float* gb = g_bkt + (size_t)(b * H_ + h) * 2 * NB * 16;
    for (int i = tid; i < 2 * NB * 16; i += 64) BS[i] = gb[i];
    const float* gq = g_qbk + (b * H_ + h) * 2 * NB;
    for (int i = tid; i < 2 * NB; i += 64) QS[i] = gq[i];
    if (tid < T_) {
        int o = (b * H_ + h) * T_ + tid;
        e1s[tid] = g_e1[o];
        e2s[tid] = g_e2[o];
        per[tid] = g_perm[o];
    }
    __syncthreads();

    if (tid < 32) {
        int arr = tid >> 4, c = tid & 15;
        float run = 0.f;
        if (arr == 0) {
            for (int r = NB - 1; r >= 0; r--) { run += BS[r * 16 + c]; BS[r * 16 + c] = run; }
        } else {
            for (int r = 0; r < NB; r++) { run += BS[(NB + r) * 16 + c]; BS[(NB + r) * 16 + c] = run; }
        }
    } else if (tid < 34) {
        int arr = tid - 32;
        float run = 0.f;
        if (arr == 0) {
            for (int r = NB - 1; r >= 0; r--) { run += QS[r]; QS[r] = run; }
        } else {
            for (int r = 0; r < NB; r++) { run += QS[NB + r]; QS[NB + r] = run; }
        }
    }
    __syncthreads();

    if (tid < T_)
        Zs[tid] = 1.0f / (e1s[tid] * QS[tid + 1] + e2s[tid] * QS[NB + tid]);
    __syncthreads();

    for (int i = tid; i < T_ * 16; i += 64) {
        int si = i >> 4, c = i & 15;
        int t = per[si];
        float o = Zs[si] * (e1s[si] * BS[(si + 1) * 16 + c] + e2s[si] * BS[(NB + si) * 16 + c]);
        out[((size_t)(b * A_) * T_ + t) * HC_ + h * C_ + c] = o + bias[h * C_ + c];
    }
}

// ---------------------------------------------------------------------------
extern "C" void kernel_launch(void* const* d_in, const int* in_sizes, int n_in,
                              void* d_out, int out_size) {
    const float* hin     = (const float*)d_in[0];
    const float* W       = (const float*)d_in[1];
    const float* att_src = (const float*)d_in[2];
    const float* att_dst = (const float*)d_in[3];
    const float* bias    = (const float*)d_in[4];
    float* out = (float*)d_out;

    cudaFuncSetAttribute(fused_kernel, cudaFuncAttributeMaxDynamicSharedMemorySize, SMEM_FUSED);

    combo_kernel<<<3136, 256>>>(hin, W, att_dst);

    dim3 gf(8, B_);
    fused_kernel<<<gf, 256, SMEM_FUSED>>>(out, bias, att_src);

    dim3 gs(H_, B_);
    finish_kernel<<<gs, 64>>>(out, bias);
}